// round 10
// baseline (speedup 1.0000x reference)
#include <cuda_runtime.h>
#include <cuda_bf16.h>
#include <math.h>
#include <stdint.h>

#define T_TOK 2048
#define HDIM  1024
#define FDIM  512
#define NE    32
#define TOPK  4
#define SLOTS (T_TOK * TOPK)

// ---------------- scratch ----------------
__device__ int   g_cnt[NE];
__device__ int   g_base[NE];
__device__ int   g_btok[NE * T_TOK];
__device__ float g_bw  [NE * T_TOK];
__device__ int   g_pe  [T_TOK * TOPK];
__device__ int   g_pp  [T_TOK * TOPK];
__device__ __nv_bfloat16 g_hhi[(size_t)SLOTS * FDIM];   // 8 MB
__device__ __nv_bfloat16 g_hlo[(size_t)SLOTS * FDIM];   // 8 MB
__device__ float g_ybuf[(size_t)SLOTS * HDIM];          // 32 MB
__device__ __nv_bfloat16 g_xh [(size_t)T_TOK * HDIM];   // 4 MB
__device__ __nv_bfloat16 g_xl [(size_t)T_TOK * HDIM];   // 4 MB

// ---------------- helpers ----------------
__device__ __forceinline__ void mma16816(float* d, const uint32_t* a, const uint32_t* b) {
    asm volatile(
        "mma.sync.aligned.m16n8k16.row.col.f32.bf16.bf16.f32 "
        "{%0,%1,%2,%3}, {%4,%5,%6,%7}, {%8,%9}, {%0,%1,%2,%3};\n"
        : "+f"(d[0]), "+f"(d[1]), "+f"(d[2]), "+f"(d[3])
        : "r"(a[0]), "r"(a[1]), "r"(a[2]), "r"(a[3]), "r"(b[0]), "r"(b[1]));
}

__device__ __forceinline__ uint32_t smem_u32(const void* p) {
    uint32_t a;
    asm("{ .reg .u64 t; cvta.to.shared.u64 t, %1; cvt.u32.u64 %0, t; }" : "=r"(a) : "l"(p));
    return a;
}
__device__ __forceinline__ void cpa16(uint32_t dst, const void* src) {
    asm volatile("cp.async.cg.shared.global [%0], [%1], 16;" :: "r"(dst), "l"(src));
}
#define CP_COMMIT() asm volatile("cp.async.commit_group;" ::: "memory")
template<int N> __device__ __forceinline__ void cp_wait() {
    asm volatile("cp.async.wait_group %0;" :: "n"(N) : "memory");
}

__device__ __forceinline__ void split2(float a, float b, uint32_t& h, uint32_t& l) {
    __nv_bfloat162 hh = __floats2bfloat162_rn(a, b);
    float2 hf = __bfloat1622float2(hh);
    __nv_bfloat162 ll = __floats2bfloat162_rn(a - hf.x, b - hf.y);
    h = *reinterpret_cast<uint32_t*>(&hh);
    l = *reinterpret_cast<uint32_t*>(&ll);
}

__device__ __forceinline__ void split8(const float* x, uint4& hv, uint4& lv) {
    uint32_t h[4], l[4];
#pragma unroll
    for (int i = 0; i < 4; i++) split2(x[2*i], x[2*i+1], h[i], l[i]);
    hv = make_uint4(h[0], h[1], h[2], h[3]);
    lv = make_uint4(l[0], l[1], l[2], l[3]);
}

// ---------------- X conversion ----------------
__global__ void convert_split(const float* __restrict__ src,
                              __nv_bfloat16* __restrict__ dh,
                              __nv_bfloat16* __restrict__ dl, int n8) {
    int i = blockIdx.x * blockDim.x + threadIdx.x;
    if (i >= n8) return;
    float x[8];
    *(float4*)&x[0] = *(const float4*)(src + 8*(size_t)i);
    *(float4*)&x[4] = *(const float4*)(src + 8*(size_t)i + 4);
    uint4 hv, lv; split8(x, hv, lv);
    *(uint4*)(dh + 8*(size_t)i) = hv;
    *(uint4*)(dl + 8*(size_t)i) = lv;
}

// ---------------- router GEMM ----------------
__global__ void router_gemm(const float* __restrict__ xr, const float* __restrict__ wr,
                            float* __restrict__ logits) {
    __shared__ float Xs[16][68];
    __shared__ float Ws[16][36];
    int tid = threadIdx.x;
    int t0  = blockIdx.x * 64;
    int tx = tid & 31, ty = tid >> 5;
    float acc[8];
#pragma unroll
    for (int j = 0; j < 8; j++) acc[j] = 0.f;
    int mL = tid >> 2, ksL = tid & 3;
    for (int k0 = 0; k0 < HDIM; k0 += 16) {
        float4 v = *(const float4*)(xr + (size_t)(t0 + mL) * HDIM + k0 + ksL * 4);
        Xs[ksL*4+0][mL] = v.x; Xs[ksL*4+1][mL] = v.y;
        Xs[ksL*4+2][mL] = v.z; Xs[ksL*4+3][mL] = v.w;
        if (tid < 128) {
            int n = tid >> 2, ks = tid & 3;
            float4 w = *(const float4*)(wr + (size_t)n * HDIM + k0 + ks * 4);
            Ws[ks*4+0][n] = w.x; Ws[ks*4+1][n] = w.y;
            Ws[ks*4+2][n] = w.z; Ws[ks*4+3][n] = w.w;
        }
        __syncthreads();
#pragma unroll
        for (int kk = 0; kk < 16; kk++) {
            float b = Ws[kk][tx];
            float4 a0 = *(const float4*)&Xs[kk][ty*8];
            float4 a1 = *(const float4*)&Xs[kk][ty*8+4];
            acc[0] += a0.x*b; acc[1] += a0.y*b; acc[2] += a0.z*b; acc[3] += a0.w*b;
            acc[4] += a1.x*b; acc[5] += a1.y*b; acc[6] += a1.z*b; acc[7] += a1.w*b;
        }
        __syncthreads();
    }
#pragma unroll
    for (int j = 0; j < 8; j++)
        logits[(size_t)(t0 + ty*8 + j) * NE + tx] = acc[j];
}

__global__ void zero_cnt() { if (threadIdx.x < NE) g_cnt[threadIdx.x] = 0; }

__global__ void topk_kernel(const float* __restrict__ logits) {
    int t = blockIdx.x * blockDim.x + threadIdx.x;
    if (t >= T_TOK) return;
    float v[NE];
#pragma unroll
    for (int e = 0; e < NE; e++) v[e] = logits[(size_t)t * NE + e];
    float val[TOPK]; int sel[TOPK];
#pragma unroll
    for (int kk = 0; kk < TOPK; kk++) {
        float best = -INFINITY; int bi = 0;
#pragma unroll
        for (int e = 0; e < NE; e++)
            if (v[e] > best) { best = v[e]; bi = e; }
        val[kk] = best; sel[kk] = bi; v[bi] = -INFINITY;
    }
    float mx = val[0];
    float w[TOPK], s = 0.f;
#pragma unroll
    for (int kk = 0; kk < TOPK; kk++) { w[kk] = expf(val[kk] - mx); s += w[kk]; }
    float inv = 1.f / s;
#pragma unroll
    for (int kk = 0; kk < TOPK; kk++) {
        int e = sel[kk];
        int pos = atomicAdd(&g_cnt[e], 1);
        g_btok[e * T_TOK + pos] = t;
        g_bw  [e * T_TOK + pos] = w[kk] * inv;
        g_pe[t * TOPK + kk] = e;
        g_pp[t * TOPK + kk] = pos;
    }
}

__global__ void prefix_kernel() {
    if (threadIdx.x == 0) {
        int s = 0;
        for (int e = 0; e < NE; e++) { g_base[e] = s; s += g_cnt[e]; }
    }
}

// ================= gate/up HMMA kernel =================
// CTA: 128 tokens x 64 F-cols, 8 warps (wm=wid&3, wn=wid>>2), 32x32 warp tiles, BK=32.
// X: pre-split bf16, cp.async 2-stage. W: fp32 LDG register-prefetch + in-kernel split.
// SMEM bytes: X stage s at s*20480 { Xh +0, Xl +10240 }; W at 40960 { Gh +0, Gl +5120,
// Uh +10240, Ul +15360 }. Total 61440. Row pitch 80B.
#define PADK 40
#define XSTG 20480
#define GU_SMEM 61440
#define DN_SMEM 51200
__global__ void __launch_bounds__(256, 2) gateup_mma(
        const float* __restrict__ wg, const float* __restrict__ wu) {
    int e   = blockIdx.z;
    int cnt = g_cnt[e];
    int m0  = blockIdx.y * 128;
    if (m0 >= cnt) return;
    int f0 = blockIdx.x * 64;

    extern __shared__ __align__(128) char smem[];
    uint32_t sb = smem_u32(smem);

    int tid = threadIdx.x, wid = tid >> 5, lane = tid & 31;
    int wm = wid & 3, wn = wid >> 2;
    int g = lane >> 2, q = lane & 3;

    // X loader: 128 rows x 2 halves of 16 bf16
    int xrow = tid >> 1, xhalf = tid & 1;
    int tokL = g_btok[e * T_TOK + min(m0 + xrow, cnt - 1)];
    const __nv_bfloat16* xhs = g_xh + (size_t)tokL * HDIM + xhalf * 16;
    const __nv_bfloat16* xls = g_xl + (size_t)tokL * HDIM + xhalf * 16;
    uint32_t xdst = sb + (uint32_t)xrow * 80 + (uint32_t)xhalf * 32;

    // W loader: 64 rows x 4 segs of 8 fp32
    int wrow = tid >> 2, wq = tid & 3;
    const float* gsrc = wg + (size_t)e * FDIM * HDIM + (size_t)(f0 + wrow) * HDIM + wq * 8;
    const float* usrc = wu + (size_t)e * FDIM * HDIM + (size_t)(f0 + wrow) * HDIM + wq * 8;
    char* wbase = smem + 40960 + wrow * 80 + wq * 16;

    float accG[2][4][4] = {}, accU[2][4][4] = {};

    const int NC = HDIM / 32;
    // prologue: W(0) regs + X(0) cp.async
    float gcur[8], ucur[8];
    *(float4*)&gcur[0] = *(const float4*)(gsrc);
    *(float4*)&gcur[4] = *(const float4*)(gsrc + 4);
    *(float4*)&ucur[0] = *(const float4*)(usrc);
    *(float4*)&ucur[4] = *(const float4*)(usrc + 4);
    cpa16(xdst, xhs); cpa16(xdst + 16, xhs + 8);
    cpa16(xdst + 10240, xls); cpa16(xdst + 10240 + 16, xls + 8);
    CP_COMMIT();

    for (int ci = 0; ci < NC; ci++) {
        // store converted W(ci) (W smem free: trailing sync of prev iter)
        {
            uint4 hv, lv;
            split8(gcur, hv, lv);
            *(uint4*)(wbase)         = hv;
            *(uint4*)(wbase + 5120)  = lv;
            split8(ucur, hv, lv);
            *(uint4*)(wbase + 10240) = hv;
            *(uint4*)(wbase + 15360) = lv;
        }
        float gn[8], un[8];
        if (ci + 1 < NC) {
            int kk = (ci + 1) * 32;
            uint32_t so = ((ci + 1) & 1) * XSTG;
            cpa16(xdst + so, xhs + kk); cpa16(xdst + so + 16, xhs + kk + 8);
            cpa16(xdst + so + 10240, xls + kk); cpa16(xdst + so + 10240 + 16, xls + kk + 8);
            CP_COMMIT();
            // W(ci+1) LDG issued now; latency overlaps the MMA below
            *(float4*)&gn[0] = *(const float4*)(gsrc + kk);
            *(float4*)&gn[4] = *(const float4*)(gsrc + kk + 4);
            *(float4*)&un[0] = *(const float4*)(usrc + kk);
            *(float4*)&un[4] = *(const float4*)(usrc + kk + 4);
            cp_wait<1>();
        } else {
            cp_wait<0>();
        }
        __syncthreads();

        const char* st = smem + (ci & 1) * XSTG;
        const __nv_bfloat16* sXh = (const __nv_bfloat16*)(st);
        const __nv_bfloat16* sXl = (const __nv_bfloat16*)(st + 10240);
        const __nv_bfloat16* sGh = (const __nv_bfloat16*)(smem + 40960);
        const __nv_bfloat16* sGl = (const __nv_bfloat16*)(smem + 40960 + 5120);
        const __nv_bfloat16* sUh = (const __nv_bfloat16*)(smem + 40960 + 10240);
        const __nv_bfloat16* sUl = (const __nv_bfloat16*)(smem + 40960 + 15360);

#pragma unroll
        for (int kt = 0; kt < 2; kt++) {
            int kc = kt * 16 + 2 * q;
            uint32_t axh[2][4], axl[2][4];
#pragma unroll
            for (int mt = 0; mt < 2; mt++) {
                int r = wm * 32 + mt * 16 + g;
                axh[mt][0] = *(const uint32_t*)&sXh[r*PADK + kc];
                axh[mt][1] = *(const uint32_t*)&sXh[(r+8)*PADK + kc];
                axh[mt][2] = *(const uint32_t*)&sXh[r*PADK + kc + 8];
                axh[mt][3] = *(const uint32_t*)&sXh[(r+8)*PADK + kc + 8];
                axl[mt][0] = *(const uint32_t*)&sXl[r*PADK + kc];
                axl[mt][1] = *(const uint32_t*)&sXl[(r+8)*PADK + kc];
                axl[mt][2] = *(const uint32_t*)&sXl[r*PADK + kc + 8];
                axl[mt][3] = *(const uint32_t*)&sXl[(r+8)*PADK + kc + 8];
            }
#pragma unroll
            for (int nt = 0; nt < 4; nt++) {
                int br = wn * 32 + nt * 8 + g;
                uint32_t bgh[2] = {*(const uint32_t*)&sGh[br*PADK + kc], *(const uint32_t*)&sGh[br*PADK + kc + 8]};
                uint32_t bgl[2] = {*(const uint32_t*)&sGl[br*PADK + kc], *(const uint32_t*)&sGl[br*PADK + kc + 8]};
                uint32_t buh[2] = {*(const uint32_t*)&sUh[br*PADK + kc], *(const uint32_t*)&sUh[br*PADK + kc + 8]};
                uint32_t bul[2] = {*(const uint32_t*)&sUl[br*PADK + kc], *(const uint32_t*)&sUl[br*PADK + kc + 8]};
#pragma unroll
                for (int mt = 0; mt < 2; mt++) {
                    mma16816(accG[mt][nt], axh[mt], bgh);
                    mma16816(accG[mt][nt], axl[mt], bgh);
                    mma16816(accG[mt][nt], axh[mt], bgl);
                    mma16816(accU[mt][nt], axh[mt], buh);
                    mma16816(accU[mt][nt], axl[mt], buh);
                    mma16816(accU[mt][nt], axh[mt], bul);
                }
            }
        }
        __syncthreads();
        if (ci + 1 < NC) {
#pragma unroll
            for (int i = 0; i < 8; i++) { gcur[i] = gn[i]; ucur[i] = un[i]; }
        }
    }

    // epilogue: h = relu(G)*U, write bf16 hi/lo
    int base = g_base[e];
#pragma unroll
    for (int mt = 0; mt < 2; mt++) {
        int lm0 = wm * 32 + mt * 16 + g;
#pragma unroll
        for (int nt = 0; nt < 4; nt++) {
            int c = f0 + wn * 32 + nt * 8 + 2 * q;
            float* Gd = accG[mt][nt];
            float* Ud = accU[mt][nt];
            float v0 = fmaxf(Gd[0], 0.f) * Ud[0];
            float v1 = fmaxf(Gd[1], 0.f) * Ud[1];
            float v2 = fmaxf(Gd[2], 0.f) * Ud[2];
            float v3 = fmaxf(Gd[3], 0.f) * Ud[3];
            uint32_t h01, l01, h23, l23;
            split2(v0, v1, h01, l01);
            split2(v2, v3, h23, l23);
            int m = m0 + lm0;
            if (m < cnt) {
                size_t slot = (size_t)base + m;
                *(uint32_t*)(g_hhi + slot * FDIM + c) = h01;
                *(uint32_t*)(g_hlo + slot * FDIM + c) = l01;
            }
            if (m + 8 < cnt) {
                size_t slot = (size_t)base + m + 8;
                *(uint32_t*)(g_hhi + slot * FDIM + c) = h23;
                *(uint32_t*)(g_hlo + slot * FDIM + c) = l23;
            }
        }
    }
}

// ================= down HMMA kernel =================
// X = h (bf16 hi/lo) cp.async 2-stage; W fp32 reg-prefetch. W smem at 40960 { Wh +0, Wl +5120 }.
__global__ void __launch_bounds__(256, 2) down_mma(const float* __restrict__ wd) {
    int e   = blockIdx.z;
    int cnt = g_cnt[e];
    int m0  = blockIdx.y * 128;
    if (m0 >= cnt) return;
    int h0 = blockIdx.x * 64;

    extern __shared__ __align__(128) char smem[];
    uint32_t sb = smem_u32(smem);

    int tid = threadIdx.x, wid = tid >> 5, lane = tid & 31;
    int wm = wid & 3, wn = wid >> 2;
    int g = lane >> 2, q = lane & 3;
    int base = g_base[e];

    int xrow = tid >> 1, xhalf = tid & 1;
    size_t slotR = (size_t)base + min(m0 + xrow, cnt - 1);
    const __nv_bfloat16* xhs = g_hhi + slotR * FDIM + xhalf * 16;
    const __nv_bfloat16* xls = g_hlo + slotR * FDIM + xhalf * 16;
    uint32_t xdst = sb + (uint32_t)xrow * 80 + (uint32_t)xhalf * 32;

    int wrow = tid >> 2, wq = tid & 3;
    const float* wsrc = wd + (size_t)e * HDIM * FDIM + (size_t)(h0 + wrow) * FDIM + wq * 8;
    char* wbase = smem + 40960 + wrow * 80 + wq * 16;

    float acc[2][4][4] = {};

    const int NC = FDIM / 32;
    float wcur[8];
    *(float4*)&wcur[0] = *(const float4*)(wsrc);
    *(float4*)&wcur[4] = *(const float4*)(wsrc + 4);
    cpa16(xdst, xhs); cpa16(xdst + 16, xhs + 8);
    cpa16(xdst + 10240, xls); cpa16(xdst + 10240 + 16, xls + 8);
    CP_COMMIT();

    for (int ci = 0; ci < NC; ci++) {
        {
            uint4 hv, lv;
            split8(wcur, hv, lv);
            *(uint4*)(wbase)        = hv;
            *(uint4*)(wbase + 5120) = lv;
        }
        float wn8[8];
        if (ci + 1 < NC) {
            int kk = (ci + 1) * 32;
            uint32_t so = ((ci + 1) & 1) * XSTG;
            cpa16(xdst + so, xhs + kk); cpa16(xdst + so + 16, xhs + kk + 8);
            cpa16(xdst + so + 10240, xls + kk); cpa16(xdst + so + 10240 + 16, xls + kk + 8);
            CP_COMMIT();
            *(float4*)&wn8[0] = *(const float4*)(wsrc + kk);
            *(float4*)&wn8[4] = *(const float4*)(wsrc + kk + 4);
            cp_wait<1>();
        } else {
            cp_wait<0>();
        }
        __syncthreads();

        const char* st = smem + (ci & 1) * XSTG;
        const __nv_bfloat16* sXh = (const __nv_bfloat16*)(st);
        const __nv_bfloat16* sXl = (const __nv_bfloat16*)(st + 10240);
        const __nv_bfloat16* sWh = (const __nv_bfloat16*)(smem + 40960);
        const __nv_bfloat16* sWl = (const __nv_bfloat16*)(smem + 40960 + 5120);

#pragma unroll
        for (int kt = 0; kt < 2; kt++) {
            int kc = kt * 16 + 2 * q;
            uint32_t axh[2][4], axl[2][4];
#pragma unroll
            for (int mt = 0; mt < 2; mt++) {
                int r = wm * 32 + mt * 16 + g;
                axh[mt][0] = *(const uint32_t*)&sXh[r*PADK + kc];
                axh[mt][1] = *(const uint32_t*)&sXh[(r+8)*PADK + kc];
                axh[mt][2] = *(const uint32_t*)&sXh[r*PADK + kc + 8];
                axh[mt][3] = *(const uint32_t*)&sXh[(r+8)*PADK + kc + 8];
                axl[mt][0] = *(const uint32_t*)&sXl[r*PADK + kc];
                axl[mt][1] = *(const uint32_t*)&sXl[(r+8)*PADK + kc];
                axl[mt][2] = *(const uint32_t*)&sXl[r*PADK + kc + 8];
                axl[mt][3] = *(const uint32_t*)&sXl[(r+8)*PADK + kc + 8];
            }
#pragma unroll
            for (int nt = 0; nt < 4; nt++) {
                int br = wn * 32 + nt * 8 + g;
                uint32_t bwh[2] = {*(const uint32_t*)&sWh[br*PADK + kc], *(const uint32_t*)&sWh[br*PADK + kc + 8]};
                uint32_t bwl[2] = {*(const uint32_t*)&sWl[br*PADK + kc], *(const uint32_t*)&sWl[br*PADK + kc + 8]};
#pragma unroll
                for (int mt = 0; mt < 2; mt++) {
                    mma16816(acc[mt][nt], axh[mt], bwh);
                    mma16816(acc[mt][nt], axl[mt], bwh);
                    mma16816(acc[mt][nt], axh[mt], bwl);
                }
            }
        }
        __syncthreads();
        if (ci + 1 < NC) {
#pragma unroll
            for (int i = 0; i < 8; i++) wcur[i] = wn8[i];
        }
    }

    // epilogue: y = acc * routing weight
#pragma unroll
    for (int mt = 0; mt < 2; mt++) {
        int lm0 = wm * 32 + mt * 16 + g;
        int m = m0 + lm0;
        float w0 = (m     < cnt) ? g_bw[e * T_TOK + m]     : 0.f;
        float w1 = (m + 8 < cnt) ? g_bw[e * T_TOK + m + 8] : 0.f;
#pragma unroll
        for (int nt = 0; nt < 4; nt++) {
            int c = h0 + wn * 32 + nt * 8 + 2 * q;
            float* D = acc[mt][nt];
            if (m < cnt) {
                float* py = g_ybuf + ((size_t)base + m) * HDIM + c;
                py[0] = D[0] * w0; py[1] = D[1] * w0;
            }
            if (m + 8 < cnt) {
                float* py = g_ybuf + ((size_t)base + m + 8) * HDIM + c;
                py[0] = D[2] * w1; py[1] = D[3] * w1;
            }
        }
    }
}

// ---------------- combine ----------------
__global__ void combine_kernel(float* __restrict__ out) {
    int t   = blockIdx.x;
    int tid = threadIdx.x;
    int sl[TOPK];
#pragma unroll
    for (int kk = 0; kk < TOPK; kk++)
        sl[kk] = g_base[g_pe[t*TOPK + kk]] + g_pp[t*TOPK + kk];
    int h = tid * 4;
    float4 a = *(const float4*)(g_ybuf + (size_t)sl[0] * HDIM + h);
    float4 b = *(const float4*)(g_ybuf + (size_t)sl[1] * HDIM + h);
    float4 c = *(const float4*)(g_ybuf + (size_t)sl[2] * HDIM + h);
    float4 d = *(const float4*)(g_ybuf + (size_t)sl[3] * HDIM + h);
    float4 r;
    r.x = a.x + b.x + c.x + d.x;
    r.y = a.y + b.y + c.y + d.y;
    r.z = a.z + b.z + c.z + d.z;
    r.w = a.w + b.w + c.w + d.w;
    *(float4*)(out + (size_t)t * HDIM + h) = r;
}

// ---------------- launch ----------------
extern "C" void kernel_launch(void* const* d_in, const int* in_sizes, int n_in,
                              void* d_out, int out_size) {
    const float* router_input = (const float*)d_in[0];
    const float* hidden       = (const float*)d_in[1];
    const float* w_router     = (const float*)d_in[2];
    const float* w_gate       = (const float*)d_in[3];
    const float* w_up         = (const float*)d_in[4];
    const float* w_down       = (const float*)d_in[5];
    float* out    = (float*)d_out;
    float* logits = out + (size_t)T_TOK * HDIM;

    static int attr_done = 0;
    if (!attr_done) {
        cudaFuncSetAttribute(gateup_mma, cudaFuncAttributeMaxDynamicSharedMemorySize, GU_SMEM);
        cudaFuncSetAttribute(down_mma,   cudaFuncAttributeMaxDynamicSharedMemorySize, DN_SMEM);
        attr_done = 1;
    }

    __nv_bfloat16 *xh, *xl;
    cudaGetSymbolAddress((void**)&xh, g_xh);
    cudaGetSymbolAddress((void**)&xl, g_xl);

    const int XN8 = T_TOK * HDIM / 8;
    convert_split<<<XN8 / 256, 256>>>(hidden, xh, xl, XN8);

    zero_cnt<<<1, 32>>>();
    router_gemm<<<T_TOK / 64, 256>>>(router_input, w_router, logits);
    topk_kernel<<<T_TOK / 256, 256>>>(logits);
    prefix_kernel<<<1, 32>>>();
    gateup_mma<<<dim3(FDIM / 64, T_TOK / 128, NE), 256, GU_SMEM>>>(w_gate, w_up);
    down_mma<<<dim3(HDIM / 64, T_TOK / 128, NE), 256, DN_SMEM>>>(w_down);
    combine_kernel<<<T_TOK, 256>>>(out);
}

// round 11
// speedup vs baseline: 1.0994x; 1.0994x over previous
#include <cuda_runtime.h>
#include <cuda_fp16.h>
#include <math.h>
#include <stdint.h>

#define T_TOK 2048
#define HDIM  1024
#define FDIM  512
#define NE    32
#define TOPK  4
#define SLOTS (T_TOK * TOPK)

// ---------------- scratch ----------------
__device__ int   g_cnt[NE];
__device__ int   g_base[NE];
__device__ int   g_btok[NE * T_TOK];
__device__ float g_bw  [NE * T_TOK];
__device__ int   g_pe  [T_TOK * TOPK];
__device__ int   g_pp  [T_TOK * TOPK];
__device__ __half g_hhi[(size_t)SLOTS * FDIM];   // 8 MB
__device__ __half g_hlo[(size_t)SLOTS * FDIM];   // 8 MB
__device__ float  g_ybuf[(size_t)SLOTS * HDIM];  // 32 MB

// ---------------- helpers ----------------
__device__ __forceinline__ void mma16816h(float* d, const uint32_t* a, const uint32_t* b) {
    asm volatile(
        "mma.sync.aligned.m16n8k16.row.col.f32.f16.f16.f32 "
        "{%0,%1,%2,%3}, {%4,%5,%6,%7}, {%8,%9}, {%0,%1,%2,%3};\n"
        : "+f"(d[0]), "+f"(d[1]), "+f"(d[2]), "+f"(d[3])
        : "r"(a[0]), "r"(a[1]), "r"(a[2]), "r"(a[3]), "r"(b[0]), "r"(b[1]));
}

// fp16 hi/lo split of a pair
__device__ __forceinline__ void split2h(float a, float b, uint32_t& h, uint32_t& l) {
    __half2 hh = __floats2half2_rn(a, b);
    float2 hf = __half22float2(hh);
    __half2 ll = __floats2half2_rn(a - hf.x, b - hf.y);
    h = *reinterpret_cast<uint32_t*>(&hh);
    l = *reinterpret_cast<uint32_t*>(&ll);
}

// split 8 fp32 -> hi uint4 + lo uint4 (fp16)
__device__ __forceinline__ void split8h(const float* x, uint4& hv, uint4& lv) {
    uint32_t h[4], l[4];
#pragma unroll
    for (int i = 0; i < 4; i++) split2h(x[2*i], x[2*i+1], h[i], l[i]);
    hv = make_uint4(h[0], h[1], h[2], h[3]);
    lv = make_uint4(l[0], l[1], l[2], l[3]);
}

// convert 8 fp32 -> 8 fp16 (single precision level, for weights)
__device__ __forceinline__ void cvt8h(const float* x, uint4& hv) {
    uint32_t h[4];
#pragma unroll
    for (int i = 0; i < 4; i++) {
        __half2 hh = __floats2half2_rn(x[2*i], x[2*i+1]);
        h[i] = *reinterpret_cast<uint32_t*>(&hh);
    }
    hv = make_uint4(h[0], h[1], h[2], h[3]);
}

// ---------------- router GEMM ----------------
__global__ void router_gemm(const float* __restrict__ xr, const float* __restrict__ wr,
                            float* __restrict__ logits) {
    __shared__ float Xs[16][68];
    __shared__ float Ws[16][36];
    int tid = threadIdx.x;
    int t0  = blockIdx.x * 64;
    int tx = tid & 31, ty = tid >> 5;
    float acc[8];
#pragma unroll
    for (int j = 0; j < 8; j++) acc[j] = 0.f;
    int mL = tid >> 2, ksL = tid & 3;
    for (int k0 = 0; k0 < HDIM; k0 += 16) {
        float4 v = *(const float4*)(xr + (size_t)(t0 + mL) * HDIM + k0 + ksL * 4);
        Xs[ksL*4+0][mL] = v.x; Xs[ksL*4+1][mL] = v.y;
        Xs[ksL*4+2][mL] = v.z; Xs[ksL*4+3][mL] = v.w;
        if (tid < 128) {
            int n = tid >> 2, ks = tid & 3;
            float4 w = *(const float4*)(wr + (size_t)n * HDIM + k0 + ks * 4);
            Ws[ks*4+0][n] = w.x; Ws[ks*4+1][n] = w.y;
            Ws[ks*4+2][n] = w.z; Ws[ks*4+3][n] = w.w;
        }
        __syncthreads();
#pragma unroll
        for (int kk = 0; kk < 16; kk++) {
            float b = Ws[kk][tx];
            float4 a0 = *(const float4*)&Xs[kk][ty*8];
            float4 a1 = *(const float4*)&Xs[kk][ty*8+4];
            acc[0] += a0.x*b; acc[1] += a0.y*b; acc[2] += a0.z*b; acc[3] += a0.w*b;
            acc[4] += a1.x*b; acc[5] += a1.y*b; acc[6] += a1.z*b; acc[7] += a1.w*b;
        }
        __syncthreads();
    }
#pragma unroll
    for (int j = 0; j < 8; j++)
        logits[(size_t)(t0 + ty*8 + j) * NE + tx] = acc[j];
}

__global__ void zero_cnt() { if (threadIdx.x < NE) g_cnt[threadIdx.x] = 0; }

__global__ void topk_kernel(const float* __restrict__ logits) {
    int t = blockIdx.x * blockDim.x + threadIdx.x;
    if (t >= T_TOK) return;
    float v[NE];
#pragma unroll
    for (int e = 0; e < NE; e++) v[e] = logits[(size_t)t * NE + e];
    float val[TOPK]; int sel[TOPK];
#pragma unroll
    for (int kk = 0; kk < TOPK; kk++) {
        float best = -INFINITY; int bi = 0;
#pragma unroll
        for (int e = 0; e < NE; e++)
            if (v[e] > best) { best = v[e]; bi = e; }
        val[kk] = best; sel[kk] = bi; v[bi] = -INFINITY;
    }
    float mx = val[0];
    float w[TOPK], s = 0.f;
#pragma unroll
    for (int kk = 0; kk < TOPK; kk++) { w[kk] = expf(val[kk] - mx); s += w[kk]; }
    float inv = 1.f / s;
#pragma unroll
    for (int kk = 0; kk < TOPK; kk++) {
        int e = sel[kk];
        int pos = atomicAdd(&g_cnt[e], 1);
        g_btok[e * T_TOK + pos] = t;
        g_bw  [e * T_TOK + pos] = w[kk] * inv;
        g_pe[t * TOPK + kk] = e;
        g_pp[t * TOPK + kk] = pos;
    }
}

__global__ void prefix_kernel() {
    if (threadIdx.x == 0) {
        int s = 0;
        for (int e = 0; e < NE; e++) { g_base[e] = s; s += g_cnt[e]; }
    }
}

// ================= gate/up HMMA kernel (fp16 2-pass) =================
// CTA: 128 tokens x 64 F-cols. 8 warps: wm=wid&3, wn=wid>>2, 32x32 warp tiles, BK=32.
// x = xh + xl (fp16 split, exact); w = fp16(w) single. out = xh*wh + xl*wh.
#define PADK 40
__global__ void __launch_bounds__(256) gateup_mma(
        const float* __restrict__ hid, const float* __restrict__ wg,
        const float* __restrict__ wu) {
    int e   = blockIdx.z;
    int cnt = g_cnt[e];
    int m0  = blockIdx.y * 128;
    if (m0 >= cnt) return;
    int f0 = blockIdx.x * 64;

    __shared__ __half sXh[128][PADK], sXl[128][PADK];
    __shared__ __half sGh[64][PADK],  sUh[64][PADK];

    int tid = threadIdx.x, wid = tid >> 5, lane = tid & 31;
    int wm = wid & 3, wn = wid >> 2;
    int g = lane >> 2, q = lane & 3;

    // loader roles (same as R4)
    int xrow = tid >> 1, xseg = tid & 1;
    int tokL = g_btok[e * T_TOK + min(m0 + xrow, cnt - 1)];
    const float* xsrc = hid + (size_t)tokL * HDIM;
    int wrow = tid >> 2, wq = tid & 3;
    const float* gsrc = wg + (size_t)e * FDIM * HDIM + (size_t)(f0 + wrow) * HDIM;
    const float* usrc = wu + (size_t)e * FDIM * HDIM + (size_t)(f0 + wrow) * HDIM;

    float accG[2][4][4] = {}, accU[2][4][4] = {};

    for (int k0 = 0; k0 < HDIM; k0 += 32) {
        // --- stage + convert ---
        {
            const float* s = xsrc + k0 + xseg * 16;
            float x[8]; uint4 hv, lv;
            *(float4*)&x[0] = *(const float4*)(s);
            *(float4*)&x[4] = *(const float4*)(s + 4);
            split8h(x, hv, lv);
            *(uint4*)&sXh[xrow][xseg*16]   = hv;
            *(uint4*)&sXl[xrow][xseg*16]   = lv;
            *(float4*)&x[0] = *(const float4*)(s + 8);
            *(float4*)&x[4] = *(const float4*)(s + 12);
            split8h(x, hv, lv);
            *(uint4*)&sXh[xrow][xseg*16+8] = hv;
            *(uint4*)&sXl[xrow][xseg*16+8] = lv;
        }
        {
            float x[8]; uint4 hv;
            const float* s = gsrc + k0 + wq * 8;
            *(float4*)&x[0] = *(const float4*)(s);
            *(float4*)&x[4] = *(const float4*)(s + 4);
            cvt8h(x, hv);
            *(uint4*)&sGh[wrow][wq*8] = hv;
            s = usrc + k0 + wq * 8;
            *(float4*)&x[0] = *(const float4*)(s);
            *(float4*)&x[4] = *(const float4*)(s + 4);
            cvt8h(x, hv);
            *(uint4*)&sUh[wrow][wq*8] = hv;
        }
        __syncthreads();

        // --- compute (2 passes per operand pair) ---
#pragma unroll
        for (int kt = 0; kt < 2; kt++) {
            int kc = kt * 16 + 2 * q;
            uint32_t axh[2][4], axl[2][4];
#pragma unroll
            for (int mt = 0; mt < 2; mt++) {
                int r = wm * 32 + mt * 16 + g;
                axh[mt][0] = *(const uint32_t*)&sXh[r][kc];
                axh[mt][1] = *(const uint32_t*)&sXh[r+8][kc];
                axh[mt][2] = *(const uint32_t*)&sXh[r][kc+8];
                axh[mt][3] = *(const uint32_t*)&sXh[r+8][kc+8];
                axl[mt][0] = *(const uint32_t*)&sXl[r][kc];
                axl[mt][1] = *(const uint32_t*)&sXl[r+8][kc];
                axl[mt][2] = *(const uint32_t*)&sXl[r][kc+8];
                axl[mt][3] = *(const uint32_t*)&sXl[r+8][kc+8];
            }
#pragma unroll
            for (int nt = 0; nt < 4; nt++) {
                int br = wn * 32 + nt * 8 + g;
                uint32_t bgh[2] = {*(const uint32_t*)&sGh[br][kc], *(const uint32_t*)&sGh[br][kc+8]};
                uint32_t buh[2] = {*(const uint32_t*)&sUh[br][kc], *(const uint32_t*)&sUh[br][kc+8]};
#pragma unroll
                for (int mt = 0; mt < 2; mt++) {
                    mma16816h(accG[mt][nt], axh[mt], bgh);
                    mma16816h(accG[mt][nt], axl[mt], bgh);
                    mma16816h(accU[mt][nt], axh[mt], buh);
                    mma16816h(accU[mt][nt], axl[mt], buh);
                }
            }
        }
        __syncthreads();
    }

    // --- epilogue: h = relu(G)*U, write fp16 hi/lo ---
    int base = g_base[e];
#pragma unroll
    for (int mt = 0; mt < 2; mt++) {
        int lm0 = wm * 32 + mt * 16 + g;
#pragma unroll
        for (int nt = 0; nt < 4; nt++) {
            int c = f0 + wn * 32 + nt * 8 + 2 * q;
            float* Gd = accG[mt][nt];
            float* Ud = accU[mt][nt];
            float v0 = fmaxf(Gd[0], 0.f) * Ud[0];
            float v1 = fmaxf(Gd[1], 0.f) * Ud[1];
            float v2 = fmaxf(Gd[2], 0.f) * Ud[2];
            float v3 = fmaxf(Gd[3], 0.f) * Ud[3];
            uint32_t h01, l01, h23, l23;
            split2h(v0, v1, h01, l01);
            split2h(v2, v3, h23, l23);
            int m = m0 + lm0;
            if (m < cnt) {
                size_t slot = (size_t)base + m;
                *(uint32_t*)(g_hhi + slot * FDIM + c) = h01;
                *(uint32_t*)(g_hlo + slot * FDIM + c) = l01;
            }
            if (m + 8 < cnt) {
                size_t slot = (size_t)base + m + 8;
                *(uint32_t*)(g_hhi + slot * FDIM + c) = h23;
                *(uint32_t*)(g_hlo + slot * FDIM + c) = l23;
            }
        }
    }
}

// ================= down HMMA kernel (fp16 2-pass) =================
__global__ void __launch_bounds__(256) down_mma(const float* __restrict__ wd) {
    int e   = blockIdx.z;
    int cnt = g_cnt[e];
    int m0  = blockIdx.y * 128;
    if (m0 >= cnt) return;
    int h0 = blockIdx.x * 64;

    __shared__ __half sXh[128][PADK], sXl[128][PADK];
    __shared__ __half sWh[64][PADK];

    int tid = threadIdx.x, wid = tid >> 5, lane = tid & 31;
    int wm = wid & 3, wn = wid >> 2;
    int g = lane >> 2, q = lane & 3;
    int base = g_base[e];

    int xrow = tid >> 1, xseg = tid & 1;
    size_t slotR = (size_t)base + min(m0 + xrow, cnt - 1);
    const __half* xhs = g_hhi + slotR * FDIM;
    const __half* xls = g_hlo + slotR * FDIM;
    int wrow = tid >> 2, wq = tid & 3;
    const float* wsrc = wd + (size_t)e * HDIM * FDIM + (size_t)(h0 + wrow) * FDIM;

    float acc[2][4][4] = {};

    for (int k0 = 0; k0 < FDIM; k0 += 32) {
        {
            int c = k0 + xseg * 16;
            *(uint4*)&sXh[xrow][xseg*16]   = *(const uint4*)(xhs + c);
            *(uint4*)&sXh[xrow][xseg*16+8] = *(const uint4*)(xhs + c + 8);
            *(uint4*)&sXl[xrow][xseg*16]   = *(const uint4*)(xls + c);
            *(uint4*)&sXl[xrow][xseg*16+8] = *(const uint4*)(xls + c + 8);
        }
        {
            float x[8]; uint4 hv;
            const float* s = wsrc + k0 + wq * 8;
            *(float4*)&x[0] = *(const float4*)(s);
            *(float4*)&x[4] = *(const float4*)(s + 4);
            cvt8h(x, hv);
            *(uint4*)&sWh[wrow][wq*8] = hv;
        }
        __syncthreads();

#pragma unroll
        for (int kt = 0; kt < 2; kt++) {
            int kc = kt * 16 + 2 * q;
            uint32_t axh[2][4], axl[2][4];
#pragma unroll
            for (int mt = 0; mt < 2; mt++) {
                int r = wm * 32 + mt * 16 + g;
                axh[mt][0] = *(const uint32_t*)&sXh[r][kc];
                axh[mt][1] = *(const uint32_t*)&sXh[r+8][kc];
                axh[mt][2] = *(const uint32_t*)&sXh[r][kc+8];
                axh[mt][3] = *(const uint32_t*)&sXh[r+8][kc+8];
                axl[mt][0] = *(const uint32_t*)&sXl[r][kc];
                axl[mt][1] = *(const uint32_t*)&sXl[r+8][kc];
                axl[mt][2] = *(const uint32_t*)&sXl[r][kc+8];
                axl[mt][3] = *(const uint32_t*)&sXl[r+8][kc+8];
            }
#pragma unroll
            for (int nt = 0; nt < 4; nt++) {
                int br = wn * 32 + nt * 8 + g;
                uint32_t bwh[2] = {*(const uint32_t*)&sWh[br][kc], *(const uint32_t*)&sWh[br][kc+8]};
#pragma unroll
                for (int mt = 0; mt < 2; mt++) {
                    mma16816h(acc[mt][nt], axh[mt], bwh);
                    mma16816h(acc[mt][nt], axl[mt], bwh);
                }
            }
        }
        __syncthreads();
    }

    // --- epilogue: y = acc * routing weight ---
#pragma unroll
    for (int mt = 0; mt < 2; mt++) {
        int lm0 = wm * 32 + mt * 16 + g;
        int m = m0 + lm0;
        float w0 = (m     < cnt) ? g_bw[e * T_TOK + m]     : 0.f;
        float w1 = (m + 8 < cnt) ? g_bw[e * T_TOK + m + 8] : 0.f;
#pragma unroll
        for (int nt = 0; nt < 4; nt++) {
            int c = h0 + wn * 32 + nt * 8 + 2 * q;
            float* D = acc[mt][nt];
            if (m < cnt) {
                float* py = g_ybuf + ((size_t)base + m) * HDIM + c;
                py[0] = D[0] * w0; py[1] = D[1] * w0;
            }
            if (m + 8 < cnt) {
                float* py = g_ybuf + ((size_t)base + m + 8) * HDIM + c;
                py[0] = D[2] * w1; py[1] = D[3] * w1;
            }
        }
    }
}

// ---------------- combine ----------------
__global__ void combine_kernel(float* __restrict__ out) {
    int t   = blockIdx.x;
    int tid = threadIdx.x;
    int sl[TOPK];
#pragma unroll
    for (int kk = 0; kk < TOPK; kk++)
        sl[kk] = g_base[g_pe[t*TOPK + kk]] + g_pp[t*TOPK + kk];
    int h = tid * 4;
    float4 a = *(const float4*)(g_ybuf + (size_t)sl[0] * HDIM + h);
    float4 b = *(const float4*)(g_ybuf + (size_t)sl[1] * HDIM + h);
    float4 c = *(const float4*)(g_ybuf + (size_t)sl[2] * HDIM + h);
    float4 d = *(const float4*)(g_ybuf + (size_t)sl[3] * HDIM + h);
    float4 r;
    r.x = a.x + b.x + c.x + d.x;
    r.y = a.y + b.y + c.y + d.y;
    r.z = a.z + b.z + c.z + d.z;
    r.w = a.w + b.w + c.w + d.w;
    *(float4*)(out + (size_t)t * HDIM + h) = r;
}

// ---------------- launch ----------------
extern "C" void kernel_launch(void* const* d_in, const int* in_sizes, int n_in,
                              void* d_out, int out_size) {
    const float* router_input = (const float*)d_in[0];
    const float* hidden       = (const float*)d_in[1];
    const float* w_router     = (const float*)d_in[2];
    const float* w_gate       = (const float*)d_in[3];
    const float* w_up         = (const float*)d_in[4];
    const float* w_down       = (const float*)d_in[5];
    float* out    = (float*)d_out;
    float* logits = out + (size_t)T_TOK * HDIM;

    zero_cnt<<<1, 32>>>();
    router_gemm<<<T_TOK / 64, 256>>>(router_input, w_router, logits);
    topk_kernel<<<T_TOK / 256, 256>>>(logits);
    prefix_kernel<<<1, 32>>>();
    gateup_mma<<<dim3(FDIM / 64, T_TOK / 128, NE), 256>>>(hidden, w_gate, w_up);
    down_mma<<<dim3(HDIM / 64, T_TOK / 128, NE), 256>>>(w_down);
    combine_kernel<<<T_TOK, 256>>>(out);
}

// round 12
// speedup vs baseline: 1.2437x; 1.1313x over previous
#include <cuda_runtime.h>
#include <cuda_fp16.h>
#include <math.h>
#include <stdint.h>

#define T_TOK 2048
#define HDIM  1024
#define FDIM  512
#define NE    32
#define TOPK  4
#define SLOTS (T_TOK * TOPK)

// ---------------- scratch ----------------
__device__ int   g_cnt[NE];
__device__ int   g_base[NE];
__device__ int   g_btok[NE * T_TOK];
__device__ float g_bw  [NE * T_TOK];
__device__ int   g_pe  [T_TOK * TOPK];
__device__ int   g_pp  [T_TOK * TOPK];
__device__ __half g_h  [(size_t)SLOTS * FDIM];   // 8 MB, single fp16 h
__device__ float  g_ybuf[(size_t)SLOTS * HDIM];  // 32 MB
__device__ __half g_xh [(size_t)T_TOK * HDIM];   // 4 MB
__device__ __half g_xl [(size_t)T_TOK * HDIM];   // 4 MB

// ---------------- helpers ----------------
__device__ __forceinline__ void mma16816h(float* d, const uint32_t* a, const uint32_t* b) {
    asm volatile(
        "mma.sync.aligned.m16n8k16.row.col.f32.f16.f16.f32 "
        "{%0,%1,%2,%3}, {%4,%5,%6,%7}, {%8,%9}, {%0,%1,%2,%3};\n"
        : "+f"(d[0]), "+f"(d[1]), "+f"(d[2]), "+f"(d[3])
        : "r"(a[0]), "r"(a[1]), "r"(a[2]), "r"(a[3]), "r"(b[0]), "r"(b[1]));
}

__device__ __forceinline__ void split2h(float a, float b, uint32_t& h, uint32_t& l) {
    __half2 hh = __floats2half2_rn(a, b);
    float2 hf = __half22float2(hh);
    __half2 ll = __floats2half2_rn(a - hf.x, b - hf.y);
    h = *reinterpret_cast<uint32_t*>(&hh);
    l = *reinterpret_cast<uint32_t*>(&ll);
}

__device__ __forceinline__ void split8h(const float* x, uint4& hv, uint4& lv) {
    uint32_t h[4], l[4];
#pragma unroll
    for (int i = 0; i < 4; i++) split2h(x[2*i], x[2*i+1], h[i], l[i]);
    hv = make_uint4(h[0], h[1], h[2], h[3]);
    lv = make_uint4(l[0], l[1], l[2], l[3]);
}

__device__ __forceinline__ void cvt8h(const float* x, uint4& hv) {
    uint32_t h[4];
#pragma unroll
    for (int i = 0; i < 4; i++) {
        __half2 hh = __floats2half2_rn(x[2*i], x[2*i+1]);
        h[i] = *reinterpret_cast<uint32_t*>(&hh);
    }
    hv = make_uint4(h[0], h[1], h[2], h[3]);
}

// ---------------- X conversion (fp16 hi/lo) ----------------
__global__ void convert_split(const float* __restrict__ src,
                              __half* __restrict__ dh,
                              __half* __restrict__ dl, int n8) {
    int i = blockIdx.x * blockDim.x + threadIdx.x;
    if (i >= n8) return;
    float x[8];
    *(float4*)&x[0] = *(const float4*)(src + 8*(size_t)i);
    *(float4*)&x[4] = *(const float4*)(src + 8*(size_t)i + 4);
    uint4 hv, lv; split8h(x, hv, lv);
    *(uint4*)(dh + 8*(size_t)i) = hv;
    *(uint4*)(dl + 8*(size_t)i) = lv;
}

// ---------------- router GEMM ----------------
__global__ void router_gemm(const float* __restrict__ xr, const float* __restrict__ wr,
                            float* __restrict__ logits) {
    __shared__ float Xs[16][68];
    __shared__ float Ws[16][36];
    int tid = threadIdx.x;
    int t0  = blockIdx.x * 64;
    int tx = tid & 31, ty = tid >> 5;
    float acc[8];
#pragma unroll
    for (int j = 0; j < 8; j++) acc[j] = 0.f;
    int mL = tid >> 2, ksL = tid & 3;
    for (int k0 = 0; k0 < HDIM; k0 += 16) {
        float4 v = *(const float4*)(xr + (size_t)(t0 + mL) * HDIM + k0 + ksL * 4);
        Xs[ksL*4+0][mL] = v.x; Xs[ksL*4+1][mL] = v.y;
        Xs[ksL*4+2][mL] = v.z; Xs[ksL*4+3][mL] = v.w;
        if (tid < 128) {
            int n = tid >> 2, ks = tid & 3;
            float4 w = *(const float4*)(wr + (size_t)n * HDIM + k0 + ks * 4);
            Ws[ks*4+0][n] = w.x; Ws[ks*4+1][n] = w.y;
            Ws[ks*4+2][n] = w.z; Ws[ks*4+3][n] = w.w;
        }
        __syncthreads();
#pragma unroll
        for (int kk = 0; kk < 16; kk++) {
            float b = Ws[kk][tx];
            float4 a0 = *(const float4*)&Xs[kk][ty*8];
            float4 a1 = *(const float4*)&Xs[kk][ty*8+4];
            acc[0] += a0.x*b; acc[1] += a0.y*b; acc[2] += a0.z*b; acc[3] += a0.w*b;
            acc[4] += a1.x*b; acc[5] += a1.y*b; acc[6] += a1.z*b; acc[7] += a1.w*b;
        }
        __syncthreads();
    }
#pragma unroll
    for (int j = 0; j < 8; j++)
        logits[(size_t)(t0 + ty*8 + j) * NE + tx] = acc[j];
}

__global__ void zero_cnt() { if (threadIdx.x < NE) g_cnt[threadIdx.x] = 0; }

__global__ void topk_kernel(const float* __restrict__ logits) {
    int t = blockIdx.x * blockDim.x + threadIdx.x;
    if (t >= T_TOK) return;
    float v[NE];
#pragma unroll
    for (int e = 0; e < NE; e++) v[e] = logits[(size_t)t * NE + e];
    float val[TOPK]; int sel[TOPK];
#pragma unroll
    for (int kk = 0; kk < TOPK; kk++) {
        float best = -INFINITY; int bi = 0;
#pragma unroll
        for (int e = 0; e < NE; e++)
            if (v[e] > best) { best = v[e]; bi = e; }
        val[kk] = best; sel[kk] = bi; v[bi] = -INFINITY;
    }
    float mx = val[0];
    float w[TOPK], s = 0.f;
#pragma unroll
    for (int kk = 0; kk < TOPK; kk++) { w[kk] = expf(val[kk] - mx); s += w[kk]; }
    float inv = 1.f / s;
#pragma unroll
    for (int kk = 0; kk < TOPK; kk++) {
        int e = sel[kk];
        int pos = atomicAdd(&g_cnt[e], 1);
        g_btok[e * T_TOK + pos] = t;
        g_bw  [e * T_TOK + pos] = w[kk] * inv;
        g_pe[t * TOPK + kk] = e;
        g_pp[t * TOPK + kk] = pos;
    }
}

__global__ void prefix_kernel() {
    if (threadIdx.x == 0) {
        int s = 0;
        for (int e = 0; e < NE; e++) { g_base[e] = s; s += g_cnt[e]; }
    }
}

// ================= gate/up HMMA kernel (fp16 2-pass, pre-split X) =================
// CTA: 128 tokens x 64 F-cols, 8 warps (wm=wid&3, wn=wid>>2), 32x32 warp tiles, BK=32.
#define PADK 40
__global__ void __launch_bounds__(256) gateup_mma(
        const float* __restrict__ wg, const float* __restrict__ wu) {
    int e   = blockIdx.z;
    int cnt = g_cnt[e];
    int m0  = blockIdx.y * 128;
    if (m0 >= cnt) return;
    int f0 = blockIdx.x * 64;

    __shared__ __half sXh[128][PADK], sXl[128][PADK];
    __shared__ __half sGh[64][PADK],  sUh[64][PADK];

    int tid = threadIdx.x, wid = tid >> 5, lane = tid & 31;
    int wm = wid & 3, wn = wid >> 2;
    int g = lane >> 2, q = lane & 3;

    // loader roles
    int xrow = tid >> 1, xseg = tid & 1;
    int tokL = g_btok[e * T_TOK + min(m0 + xrow, cnt - 1)];
    const __half* xhs = g_xh + (size_t)tokL * HDIM;
    const __half* xls = g_xl + (size_t)tokL * HDIM;
    int wrow = tid >> 2, wq = tid & 3;
    const float* gsrc = wg + (size_t)e * FDIM * HDIM + (size_t)(f0 + wrow) * HDIM;
    const float* usrc = wu + (size_t)e * FDIM * HDIM + (size_t)(f0 + wrow) * HDIM;

    float accG[2][4][4] = {}, accU[2][4][4] = {};

    for (int k0 = 0; k0 < HDIM; k0 += 32) {
        // --- stage: X direct fp16, W in-kernel convert to single fp16 ---
        {
            int c = k0 + xseg * 16;
            *(uint4*)&sXh[xrow][xseg*16]   = *(const uint4*)(xhs + c);
            *(uint4*)&sXh[xrow][xseg*16+8] = *(const uint4*)(xhs + c + 8);
            *(uint4*)&sXl[xrow][xseg*16]   = *(const uint4*)(xls + c);
            *(uint4*)&sXl[xrow][xseg*16+8] = *(const uint4*)(xls + c + 8);
        }
        {
            float x[8]; uint4 hv;
            const float* s = gsrc + k0 + wq * 8;
            *(float4*)&x[0] = *(const float4*)(s);
            *(float4*)&x[4] = *(const float4*)(s + 4);
            cvt8h(x, hv);
            *(uint4*)&sGh[wrow][wq*8] = hv;
            s = usrc + k0 + wq * 8;
            *(float4*)&x[0] = *(const float4*)(s);
            *(float4*)&x[4] = *(const float4*)(s + 4);
            cvt8h(x, hv);
            *(uint4*)&sUh[wrow][wq*8] = hv;
        }
        __syncthreads();

        // --- compute (2 passes: xh*w + xl*w) ---
#pragma unroll
        for (int kt = 0; kt < 2; kt++) {
            int kc = kt * 16 + 2 * q;
            uint32_t axh[2][4], axl[2][4];
#pragma unroll
            for (int mt = 0; mt < 2; mt++) {
                int r = wm * 32 + mt * 16 + g;
                axh[mt][0] = *(const uint32_t*)&sXh[r][kc];
                axh[mt][1] = *(const uint32_t*)&sXh[r+8][kc];
                axh[mt][2] = *(const uint32_t*)&sXh[r][kc+8];
                axh[mt][3] = *(const uint32_t*)&sXh[r+8][kc+8];
                axl[mt][0] = *(const uint32_t*)&sXl[r][kc];
                axl[mt][1] = *(const uint32_t*)&sXl[r+8][kc];
                axl[mt][2] = *(const uint32_t*)&sXl[r][kc+8];
                axl[mt][3] = *(const uint32_t*)&sXl[r+8][kc+8];
            }
#pragma unroll
            for (int nt = 0; nt < 4; nt++) {
                int br = wn * 32 + nt * 8 + g;
                uint32_t bgh[2] = {*(const uint32_t*)&sGh[br][kc], *(const uint32_t*)&sGh[br][kc+8]};
                uint32_t buh[2] = {*(const uint32_t*)&sUh[br][kc], *(const uint32_t*)&sUh[br][kc+8]};
#pragma unroll
                for (int mt = 0; mt < 2; mt++) {
                    mma16816h(accG[mt][nt], axh[mt], bgh);
                    mma16816h(accG[mt][nt], axl[mt], bgh);
                    mma16816h(accU[mt][nt], axh[mt], buh);
                    mma16816h(accU[mt][nt], axl[mt], buh);
                }
            }
        }
        __syncthreads();
    }

    // --- epilogue: h = relu(G)*U, write single fp16 ---
    int base = g_base[e];
#pragma unroll
    for (int mt = 0; mt < 2; mt++) {
        int lm0 = wm * 32 + mt * 16 + g;
#pragma unroll
        for (int nt = 0; nt < 4; nt++) {
            int c = f0 + wn * 32 + nt * 8 + 2 * q;
            float* Gd = accG[mt][nt];
            float* Ud = accU[mt][nt];
            float v0 = fmaxf(Gd[0], 0.f) * Ud[0];
            float v1 = fmaxf(Gd[1], 0.f) * Ud[1];
            float v2 = fmaxf(Gd[2], 0.f) * Ud[2];
            float v3 = fmaxf(Gd[3], 0.f) * Ud[3];
            __half2 h01 = __floats2half2_rn(v0, v1);
            __half2 h23 = __floats2half2_rn(v2, v3);
            int m = m0 + lm0;
            if (m < cnt)
                *(__half2*)(g_h + ((size_t)base + m) * FDIM + c) = h01;
            if (m + 8 < cnt)
                *(__half2*)(g_h + ((size_t)base + m + 8) * FDIM + c) = h23;
        }
    }
}

// ================= down HMMA kernel (fp16 single-pass, BN=128) =================
// CTA: 128 slots x 128 H-cols, 8 warps (wm=wid&3 -> 32 M-rows, wn=wid>>2 -> 64 N-cols).
__global__ void __launch_bounds__(256) down_mma(const float* __restrict__ wd) {
    int e   = blockIdx.z;
    int cnt = g_cnt[e];
    int m0  = blockIdx.y * 128;
    if (m0 >= cnt) return;
    int h0 = blockIdx.x * 128;

    __shared__ __half sX[128][PADK];
    __shared__ __half sW[128][PADK];

    int tid = threadIdx.x, wid = tid >> 5, lane = tid & 31;
    int wm = wid & 3, wn = wid >> 2;
    int g = lane >> 2, q = lane & 3;
    int base = g_base[e];

    // X loader: 128 rows, 2 threads/row x 16 halfs
    int xrow = tid >> 1, xseg = tid & 1;
    size_t slotR = (size_t)base + min(m0 + xrow, cnt - 1);
    const __half* xs = g_h + slotR * FDIM;
    // W loader: 128 rows, 2 threads/row x 16 fp32
    int wrow = tid >> 1, wseg = tid & 1;
    const float* wsrc = wd + (size_t)e * HDIM * FDIM + (size_t)(h0 + wrow) * FDIM + wseg * 16;

    float acc[2][8][4] = {};

    for (int k0 = 0; k0 < FDIM; k0 += 32) {
        {
            int c = k0 + xseg * 16;
            *(uint4*)&sX[xrow][xseg*16]   = *(const uint4*)(xs + c);
            *(uint4*)&sX[xrow][xseg*16+8] = *(const uint4*)(xs + c + 8);
        }
        {
            float x[8]; uint4 hv;
            const float* s = wsrc + k0;
            *(float4*)&x[0] = *(const float4*)(s);
            *(float4*)&x[4] = *(const float4*)(s + 4);
            cvt8h(x, hv);
            *(uint4*)&sW[wrow][wseg*16] = hv;
            *(float4*)&x[0] = *(const float4*)(s + 8);
            *(float4*)&x[4] = *(const float4*)(s + 12);
            cvt8h(x, hv);
            *(uint4*)&sW[wrow][wseg*16+8] = hv;
        }
        __syncthreads();

#pragma unroll
        for (int kt = 0; kt < 2; kt++) {
            int kc = kt * 16 + 2 * q;
            uint32_t ax[2][4];
#pragma unroll
            for (int mt = 0; mt < 2; mt++) {
                int r = wm * 32 + mt * 16 + g;
                ax[mt][0] = *(const uint32_t*)&sX[r][kc];
                ax[mt][1] = *(const uint32_t*)&sX[r+8][kc];
                ax[mt][2] = *(const uint32_t*)&sX[r][kc+8];
                ax[mt][3] = *(const uint32_t*)&sX[r+8][kc+8];
            }
#pragma unroll
            for (int nt = 0; nt < 8; nt++) {
                int br = wn * 64 + nt * 8 + g;
                uint32_t bw[2] = {*(const uint32_t*)&sW[br][kc], *(const uint32_t*)&sW[br][kc+8]};
#pragma unroll
                for (int mt = 0; mt < 2; mt++)
                    mma16816h(acc[mt][nt], ax[mt], bw);
            }
        }
        __syncthreads();
    }

    // --- epilogue: y = acc * routing weight ---
#pragma unroll
    for (int mt = 0; mt < 2; mt++) {
        int lm0 = wm * 32 + mt * 16 + g;
        int m = m0 + lm0;
        float w0 = (m     < cnt) ? g_bw[e * T_TOK + m]     : 0.f;
        float w1 = (m + 8 < cnt) ? g_bw[e * T_TOK + m + 8] : 0.f;
#pragma unroll
        for (int nt = 0; nt < 8; nt++) {
            int c = h0 + wn * 64 + nt * 8 + 2 * q;
            float* D = acc[mt][nt];
            if (m < cnt) {
                float* py = g_ybuf + ((size_t)base + m) * HDIM + c;
                py[0] = D[0] * w0; py[1] = D[1] * w0;
            }
            if (m + 8 < cnt) {
                float* py = g_ybuf + ((size_t)base + m + 8) * HDIM + c;
                py[0] = D[2] * w1; py[1] = D[3] * w1;
            }
        }
    }
}

// ---------------- combine ----------------
__global__ void combine_kernel(float* __restrict__ out) {
    int t   = blockIdx.x;
    int tid = threadIdx.x;
    int sl[TOPK];
#pragma unroll
    for (int kk = 0; kk < TOPK; kk++)
        sl[kk] = g_base[g_pe[t*TOPK + kk]] + g_pp[t*TOPK + kk];
    int h = tid * 4;
    float4 a = *(const float4*)(g_ybuf + (size_t)sl[0] * HDIM + h);
    float4 b = *(const float4*)(g_ybuf + (size_t)sl[1] * HDIM + h);
    float4 c = *(const float4*)(g_ybuf + (size_t)sl[2] * HDIM + h);
    float4 d = *(const float4*)(g_ybuf + (size_t)sl[3] * HDIM + h);
    float4 r;
    r.x = a.x + b.x + c.x + d.x;
    r.y = a.y + b.y + c.y + d.y;
    r.z = a.z + b.z + c.z + d.z;
    r.w = a.w + b.w + c.w + d.w;
    *(float4*)(out + (size_t)t * HDIM + h) = r;
}

// ---------------- launch ----------------
extern "C" void kernel_launch(void* const* d_in, const int* in_sizes, int n_in,
                              void* d_out, int out_size) {
    const float* router_input = (const float*)d_in[0];
    const float* hidden       = (const float*)d_in[1];
    const float* w_router     = (const float*)d_in[2];
    const float* w_gate       = (const float*)d_in[3];
    const float* w_up         = (const float*)d_in[4];
    const float* w_down       = (const float*)d_in[5];
    float* out    = (float*)d_out;
    float* logits = out + (size_t)T_TOK * HDIM;

    __half *xh, *xl;
    cudaGetSymbolAddress((void**)&xh, g_xh);
    cudaGetSymbolAddress((void**)&xl, g_xl);

    const int XN8 = T_TOK * HDIM / 8;
    convert_split<<<XN8 / 256, 256>>>(hidden, xh, xl, XN8);

    zero_cnt<<<1, 32>>>();
    router_gemm<<<T_TOK / 64, 256>>>(router_input, w_router, logits);
    topk_kernel<<<T_TOK / 256, 256>>>(logits);
    prefix_kernel<<<1, 32>>>();
    gateup_mma<<<dim3(FDIM / 64, T_TOK / 128, NE), 256>>>(w_gate, w_up);
    down_mma<<<dim3(HDIM / 128, T_TOK / 128, NE), 256>>>(w_down);
    combine_kernel<<<T_TOK, 256>>>(out);
}

// round 13
// speedup vs baseline: 1.4447x; 1.1617x over previous
#include <cuda_runtime.h>
#include <cuda_fp16.h>
#include <math.h>
#include <stdint.h>

#define T_TOK 2048
#define HDIM  1024
#define FDIM  512
#define NE    32
#define TOPK  4
#define SLOTS (T_TOK * TOPK)

// ---------------- scratch ----------------
__device__ int   g_cnt[NE];
__device__ int   g_base[NE];
__device__ int   g_btok[NE * T_TOK];
__device__ float g_bw  [NE * T_TOK];
__device__ int   g_pe  [T_TOK * TOPK];
__device__ int   g_pp  [T_TOK * TOPK];
__device__ __half g_h  [(size_t)SLOTS * FDIM];   // 8 MB, fp16 h
__device__ float  g_ybuf[(size_t)SLOTS * HDIM];  // 32 MB
__device__ __half g_x16[(size_t)T_TOK * HDIM];   // 4 MB, fp16 hidden

// ---------------- helpers ----------------
__device__ __forceinline__ void mma16816h(float* d, const uint32_t* a, const uint32_t* b) {
    asm volatile(
        "mma.sync.aligned.m16n8k16.row.col.f32.f16.f16.f32 "
        "{%0,%1,%2,%3}, {%4,%5,%6,%7}, {%8,%9}, {%0,%1,%2,%3};\n"
        : "+f"(d[0]), "+f"(d[1]), "+f"(d[2]), "+f"(d[3])
        : "r"(a[0]), "r"(a[1]), "r"(a[2]), "r"(a[3]), "r"(b[0]), "r"(b[1]));
}

__device__ __forceinline__ void cvt8h(const float* x, uint4& hv) {
    uint32_t h[4];
#pragma unroll
    for (int i = 0; i < 4; i++) {
        __half2 hh = __floats2half2_rn(x[2*i], x[2*i+1]);
        h[i] = *reinterpret_cast<uint32_t*>(&hh);
    }
    hv = make_uint4(h[0], h[1], h[2], h[3]);
}

// ---------------- X conversion (single fp16) ----------------
__global__ void convert_f16(const float* __restrict__ src,
                            __half* __restrict__ dst, int n8) {
    int i = blockIdx.x * blockDim.x + threadIdx.x;
    if (i >= n8) return;
    float x[8];
    *(float4*)&x[0] = *(const float4*)(src + 8*(size_t)i);
    *(float4*)&x[4] = *(const float4*)(src + 8*(size_t)i + 4);
    uint4 hv; cvt8h(x, hv);
    *(uint4*)(dst + 8*(size_t)i) = hv;
}

// ---------------- router GEMM ----------------
__global__ void router_gemm(const float* __restrict__ xr, const float* __restrict__ wr,
                            float* __restrict__ logits) {
    __shared__ float Xs[16][68];
    __shared__ float Ws[16][36];
    int tid = threadIdx.x;
    int t0  = blockIdx.x * 64;
    int tx = tid & 31, ty = tid >> 5;
    float acc[8];
#pragma unroll
    for (int j = 0; j < 8; j++) acc[j] = 0.f;
    int mL = tid >> 2, ksL = tid & 3;
    for (int k0 = 0; k0 < HDIM; k0 += 16) {
        float4 v = *(const float4*)(xr + (size_t)(t0 + mL) * HDIM + k0 + ksL * 4);
        Xs[ksL*4+0][mL] = v.x; Xs[ksL*4+1][mL] = v.y;
        Xs[ksL*4+2][mL] = v.z; Xs[ksL*4+3][mL] = v.w;
        if (tid < 128) {
            int n = tid >> 2, ks = tid & 3;
            float4 w = *(const float4*)(wr + (size_t)n * HDIM + k0 + ks * 4);
            Ws[ks*4+0][n] = w.x; Ws[ks*4+1][n] = w.y;
            Ws[ks*4+2][n] = w.z; Ws[ks*4+3][n] = w.w;
        }
        __syncthreads();
#pragma unroll
        for (int kk = 0; kk < 16; kk++) {
            float b = Ws[kk][tx];
            float4 a0 = *(const float4*)&Xs[kk][ty*8];
            float4 a1 = *(const float4*)&Xs[kk][ty*8+4];
            acc[0] += a0.x*b; acc[1] += a0.y*b; acc[2] += a0.z*b; acc[3] += a0.w*b;
            acc[4] += a1.x*b; acc[5] += a1.y*b; acc[6] += a1.z*b; acc[7] += a1.w*b;
        }
        __syncthreads();
    }
#pragma unroll
    for (int j = 0; j < 8; j++)
        logits[(size_t)(t0 + ty*8 + j) * NE + tx] = acc[j];
}

__global__ void zero_cnt() { if (threadIdx.x < NE) g_cnt[threadIdx.x] = 0; }

__global__ void topk_kernel(const float* __restrict__ logits) {
    int t = blockIdx.x * blockDim.x + threadIdx.x;
    if (t >= T_TOK) return;
    float v[NE];
#pragma unroll
    for (int e = 0; e < NE; e++) v[e] = logits[(size_t)t * NE + e];
    float val[TOPK]; int sel[TOPK];
#pragma unroll
    for (int kk = 0; kk < TOPK; kk++) {
        float best = -INFINITY; int bi = 0;
#pragma unroll
        for (int e = 0; e < NE; e++)
            if (v[e] > best) { best = v[e]; bi = e; }
        val[kk] = best; sel[kk] = bi; v[bi] = -INFINITY;
    }
    float mx = val[0];
    float w[TOPK], s = 0.f;
#pragma unroll
    for (int kk = 0; kk < TOPK; kk++) { w[kk] = expf(val[kk] - mx); s += w[kk]; }
    float inv = 1.f / s;
#pragma unroll
    for (int kk = 0; kk < TOPK; kk++) {
        int e = sel[kk];
        int pos = atomicAdd(&g_cnt[e], 1);
        g_btok[e * T_TOK + pos] = t;
        g_bw  [e * T_TOK + pos] = w[kk] * inv;
        g_pe[t * TOPK + kk] = e;
        g_pp[t * TOPK + kk] = pos;
    }
}

__global__ void prefix_kernel() {
    if (threadIdx.x == 0) {
        int s = 0;
        for (int e = 0; e < NE; e++) { g_base[e] = s; s += g_cnt[e]; }
    }
}

// ================= gate/up HMMA kernel (fp16 single-pass) =================
// CTA: 128 tokens x 64 F-cols, 8 warps (wm=wid&3, wn=wid>>2), 32x32 warp tiles, BK=32.
#define PADK 40
__global__ void __launch_bounds__(256) gateup_mma(
        const float* __restrict__ wg, const float* __restrict__ wu) {
    int e   = blockIdx.z;
    int cnt = g_cnt[e];
    int m0  = blockIdx.y * 128;
    if (m0 >= cnt) return;
    int f0 = blockIdx.x * 64;

    __shared__ __half sX[128][PADK];
    __shared__ __half sGh[64][PADK], sUh[64][PADK];

    int tid = threadIdx.x, wid = tid >> 5, lane = tid & 31;
    int wm = wid & 3, wn = wid >> 2;
    int g = lane >> 2, q = lane & 3;

    // loader roles
    int xrow = tid >> 1, xseg = tid & 1;
    int tokL = g_btok[e * T_TOK + min(m0 + xrow, cnt - 1)];
    const __half* xs = g_x16 + (size_t)tokL * HDIM;
    int wrow = tid >> 2, wq = tid & 3;
    const float* gsrc = wg + (size_t)e * FDIM * HDIM + (size_t)(f0 + wrow) * HDIM;
    const float* usrc = wu + (size_t)e * FDIM * HDIM + (size_t)(f0 + wrow) * HDIM;

    float accG[2][4][4] = {}, accU[2][4][4] = {};

    for (int k0 = 0; k0 < HDIM; k0 += 32) {
        // --- stage: X direct fp16, W convert to fp16 ---
        {
            int c = k0 + xseg * 16;
            *(uint4*)&sX[xrow][xseg*16]   = *(const uint4*)(xs + c);
            *(uint4*)&sX[xrow][xseg*16+8] = *(const uint4*)(xs + c + 8);
        }
        {
            float x[8]; uint4 hv;
            const float* s = gsrc + k0 + wq * 8;
            *(float4*)&x[0] = *(const float4*)(s);
            *(float4*)&x[4] = *(const float4*)(s + 4);
            cvt8h(x, hv);
            *(uint4*)&sGh[wrow][wq*8] = hv;
            s = usrc + k0 + wq * 8;
            *(float4*)&x[0] = *(const float4*)(s);
            *(float4*)&x[4] = *(const float4*)(s + 4);
            cvt8h(x, hv);
            *(uint4*)&sUh[wrow][wq*8] = hv;
        }
        __syncthreads();

        // --- compute: single pass per operand ---
#pragma unroll
        for (int kt = 0; kt < 2; kt++) {
            int kc = kt * 16 + 2 * q;
            uint32_t ax[2][4];
#pragma unroll
            for (int mt = 0; mt < 2; mt++) {
                int r = wm * 32 + mt * 16 + g;
                ax[mt][0] = *(const uint32_t*)&sX[r][kc];
                ax[mt][1] = *(const uint32_t*)&sX[r+8][kc];
                ax[mt][2] = *(const uint32_t*)&sX[r][kc+8];
                ax[mt][3] = *(const uint32_t*)&sX[r+8][kc+8];
            }
#pragma unroll
            for (int nt = 0; nt < 4; nt++) {
                int br = wn * 32 + nt * 8 + g;
                uint32_t bgh[2] = {*(const uint32_t*)&sGh[br][kc], *(const uint32_t*)&sGh[br][kc+8]};
                uint32_t buh[2] = {*(const uint32_t*)&sUh[br][kc], *(const uint32_t*)&sUh[br][kc+8]};
#pragma unroll
                for (int mt = 0; mt < 2; mt++) {
                    mma16816h(accG[mt][nt], ax[mt], bgh);
                    mma16816h(accU[mt][nt], ax[mt], buh);
                }
            }
        }
        __syncthreads();
    }

    // --- epilogue: h = relu(G)*U, write fp16 ---
    int base = g_base[e];
#pragma unroll
    for (int mt = 0; mt < 2; mt++) {
        int lm0 = wm * 32 + mt * 16 + g;
#pragma unroll
        for (int nt = 0; nt < 4; nt++) {
            int c = f0 + wn * 32 + nt * 8 + 2 * q;
            float* Gd = accG[mt][nt];
            float* Ud = accU[mt][nt];
            float v0 = fmaxf(Gd[0], 0.f) * Ud[0];
            float v1 = fmaxf(Gd[1], 0.f) * Ud[1];
            float v2 = fmaxf(Gd[2], 0.f) * Ud[2];
            float v3 = fmaxf(Gd[3], 0.f) * Ud[3];
            __half2 h01 = __floats2half2_rn(v0, v1);
            __half2 h23 = __floats2half2_rn(v2, v3);
            int m = m0 + lm0;
            if (m < cnt)
                *(__half2*)(g_h + ((size_t)base + m) * FDIM + c) = h01;
            if (m + 8 < cnt)
                *(__half2*)(g_h + ((size_t)base + m + 8) * FDIM + c) = h23;
        }
    }
}

// ================= down HMMA kernel (fp16 single-pass, BN=128) =================
__global__ void __launch_bounds__(256) down_mma(const float* __restrict__ wd) {
    int e   = blockIdx.z;
    int cnt = g_cnt[e];
    int m0  = blockIdx.y * 128;
    if (m0 >= cnt) return;
    int h0 = blockIdx.x * 128;

    __shared__ __half sX[128][PADK];
    __shared__ __half sW[128][PADK];

    int tid = threadIdx.x, wid = tid >> 5, lane = tid & 31;
    int wm = wid & 3, wn = wid >> 2;
    int g = lane >> 2, q = lane & 3;
    int base = g_base[e];

    int xrow = tid >> 1, xseg = tid & 1;
    size_t slotR = (size_t)base + min(m0 + xrow, cnt - 1);
    const __half* xs = g_h + slotR * FDIM;
    int wrow = tid >> 1, wseg = tid & 1;
    const float* wsrc = wd + (size_t)e * HDIM * FDIM + (size_t)(h0 + wrow) * FDIM + wseg * 16;

    float acc[2][8][4] = {};

    for (int k0 = 0; k0 < FDIM; k0 += 32) {
        {
            int c = k0 + xseg * 16;
            *(uint4*)&sX[xrow][xseg*16]   = *(const uint4*)(xs + c);
            *(uint4*)&sX[xrow][xseg*16+8] = *(const uint4*)(xs + c + 8);
        }
        {
            float x[8]; uint4 hv;
            const float* s = wsrc + k0;
            *(float4*)&x[0] = *(const float4*)(s);
            *(float4*)&x[4] = *(const float4*)(s + 4);
            cvt8h(x, hv);
            *(uint4*)&sW[wrow][wseg*16] = hv;
            *(float4*)&x[0] = *(const float4*)(s + 8);
            *(float4*)&x[4] = *(const float4*)(s + 12);
            cvt8h(x, hv);
            *(uint4*)&sW[wrow][wseg*16+8] = hv;
        }
        __syncthreads();

#pragma unroll
        for (int kt = 0; kt < 2; kt++) {
            int kc = kt * 16 + 2 * q;
            uint32_t ax[2][4];
#pragma unroll
            for (int mt = 0; mt < 2; mt++) {
                int r = wm * 32 + mt * 16 + g;
                ax[mt][0] = *(const uint32_t*)&sX[r][kc];
                ax[mt][1] = *(const uint32_t*)&sX[r+8][kc];
                ax[mt][2] = *(const uint32_t*)&sX[r][kc+8];
                ax[mt][3] = *(const uint32_t*)&sX[r+8][kc+8];
            }
#pragma unroll
            for (int nt = 0; nt < 8; nt++) {
                int br = wn * 64 + nt * 8 + g;
                uint32_t bw[2] = {*(const uint32_t*)&sW[br][kc], *(const uint32_t*)&sW[br][kc+8]};
#pragma unroll
                for (int mt = 0; mt < 2; mt++)
                    mma16816h(acc[mt][nt], ax[mt], bw);
            }
        }
        __syncthreads();
    }

    // --- epilogue: y = acc * routing weight ---
#pragma unroll
    for (int mt = 0; mt < 2; mt++) {
        int lm0 = wm * 32 + mt * 16 + g;
        int m = m0 + lm0;
        float w0 = (m     < cnt) ? g_bw[e * T_TOK + m]     : 0.f;
        float w1 = (m + 8 < cnt) ? g_bw[e * T_TOK + m + 8] : 0.f;
#pragma unroll
        for (int nt = 0; nt < 8; nt++) {
            int c = h0 + wn * 64 + nt * 8 + 2 * q;
            float* D = acc[mt][nt];
            if (m < cnt) {
                float* py = g_ybuf + ((size_t)base + m) * HDIM + c;
                py[0] = D[0] * w0; py[1] = D[1] * w0;
            }
            if (m + 8 < cnt) {
                float* py = g_ybuf + ((size_t)base + m + 8) * HDIM + c;
                py[0] = D[2] * w1; py[1] = D[3] * w1;
            }
        }
    }
}

// ---------------- combine ----------------
__global__ void combine_kernel(float* __restrict__ out) {
    int t   = blockIdx.x;
    int tid = threadIdx.x;
    int sl[TOPK];
#pragma unroll
    for (int kk = 0; kk < TOPK; kk++)
        sl[kk] = g_base[g_pe[t*TOPK + kk]] + g_pp[t*TOPK + kk];
    int h = tid * 4;
    float4 a = *(const float4*)(g_ybuf + (size_t)sl[0] * HDIM + h);
    float4 b = *(const float4*)(g_ybuf + (size_t)sl[1] * HDIM + h);
    float4 c = *(const float4*)(g_ybuf + (size_t)sl[2] * HDIM + h);
    float4 d = *(const float4*)(g_ybuf + (size_t)sl[3] * HDIM + h);
    float4 r;
    r.x = a.x + b.x + c.x + d.x;
    r.y = a.y + b.y + c.y + d.y;
    r.z = a.z + b.z + c.z + d.z;
    r.w = a.w + b.w + c.w + d.w;
    *(float4*)(out + (size_t)t * HDIM + h) = r;
}

// ---------------- launch ----------------
extern "C" void kernel_launch(void* const* d_in, const int* in_sizes, int n_in,
                              void* d_out, int out_size) {
    const float* router_input = (const float*)d_in[0];
    const float* hidden       = (const float*)d_in[1];
    const float* w_router     = (const float*)d_in[2];
    const float* w_gate       = (const float*)d_in[3];
    const float* w_up         = (const float*)d_in[4];
    const float* w_down       = (const float*)d_in[5];
    float* out    = (float*)d_out;
    float* logits = out + (size_t)T_TOK * HDIM;

    __half *x16;
    cudaGetSymbolAddress((void**)&x16, g_x16);

    const int XN8 = T_TOK * HDIM / 8;
    convert_f16<<<XN8 / 256, 256>>>(hidden, x16, XN8);

    zero_cnt<<<1, 32>>>();
    router_gemm<<<T_TOK / 64, 256>>>(router_input, w_router, logits);
    topk_kernel<<<T_TOK / 256, 256>>>(logits);
    prefix_kernel<<<1, 32>>>();
    gateup_mma<<<dim3(FDIM / 64, T_TOK / 128, NE), 256>>>(w_gate, w_up);
    down_mma<<<dim3(HDIM / 128, T_TOK / 128, NE), 256>>>(w_down);
    combine_kernel<<<T_TOK, 256>>>(out);
}

// round 14
// speedup vs baseline: 1.5868x; 1.0984x over previous
#include <cuda_runtime.h>
#include <cuda_fp16.h>
#include <math.h>
#include <stdint.h>

#define T_TOK 2048
#define HDIM  1024
#define FDIM  512
#define NE    32
#define TOPK  4
#define SLOTS (T_TOK * TOPK)

// ---------------- scratch ----------------
__device__ int   g_cnt[NE];
__device__ int   g_base[NE];
__device__ int   g_btok[NE * T_TOK];
__device__ float g_bw  [NE * T_TOK];
__device__ int   g_pe  [T_TOK * TOPK];
__device__ int   g_pp  [T_TOK * TOPK];
__device__ __half g_h  [(size_t)SLOTS * FDIM];   // 8 MB
__device__ float  g_ybuf[(size_t)SLOTS * HDIM];  // 32 MB
__device__ __half g_x16[(size_t)T_TOK * HDIM];   // 4 MB

// ---------------- helpers ----------------
__device__ __forceinline__ void mma16816h(float* d, const uint32_t* a, const uint32_t* b) {
    asm volatile(
        "mma.sync.aligned.m16n8k16.row.col.f32.f16.f16.f32 "
        "{%0,%1,%2,%3}, {%4,%5,%6,%7}, {%8,%9}, {%0,%1,%2,%3};\n"
        : "+f"(d[0]), "+f"(d[1]), "+f"(d[2]), "+f"(d[3])
        : "r"(a[0]), "r"(a[1]), "r"(a[2]), "r"(a[3]), "r"(b[0]), "r"(b[1]));
}

__device__ __forceinline__ uint32_t smem_u32(const void* p) {
    uint32_t a;
    asm("{ .reg .u64 t; cvta.to.shared.u64 t, %1; cvt.u32.u64 %0, t; }" : "=r"(a) : "l"(p));
    return a;
}
__device__ __forceinline__ void cpa16(uint32_t dst, const void* src) {
    asm volatile("cp.async.cg.shared.global [%0], [%1], 16;" :: "r"(dst), "l"(src));
}
#define CP_COMMIT() asm volatile("cp.async.commit_group;" ::: "memory")
template<int N> __device__ __forceinline__ void cp_wait() {
    asm volatile("cp.async.wait_group %0;" :: "n"(N) : "memory");
}

__device__ __forceinline__ void cvt8h(const float* x, uint4& hv) {
    uint32_t h[4];
#pragma unroll
    for (int i = 0; i < 4; i++) {
        __half2 hh = __floats2half2_rn(x[2*i], x[2*i+1]);
        h[i] = *reinterpret_cast<uint32_t*>(&hh);
    }
    hv = make_uint4(h[0], h[1], h[2], h[3]);
}

// ---------------- X conversion ----------------
__global__ void convert_f16(const float* __restrict__ src,
                            __half* __restrict__ dst, int n8) {
    int i = blockIdx.x * blockDim.x + threadIdx.x;
    if (i >= n8) return;
    float x[8];
    *(float4*)&x[0] = *(const float4*)(src + 8*(size_t)i);
    *(float4*)&x[4] = *(const float4*)(src + 8*(size_t)i + 4);
    uint4 hv; cvt8h(x, hv);
    *(uint4*)(dst + 8*(size_t)i) = hv;
}

// ---------------- router GEMM ----------------
__global__ void router_gemm(const float* __restrict__ xr, const float* __restrict__ wr,
                            float* __restrict__ logits) {
    __shared__ float Xs[16][68];
    __shared__ float Ws[16][36];
    int tid = threadIdx.x;
    int t0  = blockIdx.x * 64;
    int tx = tid & 31, ty = tid >> 5;
    float acc[8];
#pragma unroll
    for (int j = 0; j < 8; j++) acc[j] = 0.f;
    int mL = tid >> 2, ksL = tid & 3;
    for (int k0 = 0; k0 < HDIM; k0 += 16) {
        float4 v = *(const float4*)(xr + (size_t)(t0 + mL) * HDIM + k0 + ksL * 4);
        Xs[ksL*4+0][mL] = v.x; Xs[ksL*4+1][mL] = v.y;
        Xs[ksL*4+2][mL] = v.z; Xs[ksL*4+3][mL] = v.w;
        if (tid < 128) {
            int n = tid >> 2, ks = tid & 3;
            float4 w = *(const float4*)(wr + (size_t)n * HDIM + k0 + ks * 4);
            Ws[ks*4+0][n] = w.x; Ws[ks*4+1][n] = w.y;
            Ws[ks*4+2][n] = w.z; Ws[ks*4+3][n] = w.w;
        }
        __syncthreads();
#pragma unroll
        for (int kk = 0; kk < 16; kk++) {
            float b = Ws[kk][tx];
            float4 a0 = *(const float4*)&Xs[kk][ty*8];
            float4 a1 = *(const float4*)&Xs[kk][ty*8+4];
            acc[0] += a0.x*b; acc[1] += a0.y*b; acc[2] += a0.z*b; acc[3] += a0.w*b;
            acc[4] += a1.x*b; acc[5] += a1.y*b; acc[6] += a1.z*b; acc[7] += a1.w*b;
        }
        __syncthreads();
    }
#pragma unroll
    for (int j = 0; j < 8; j++)
        logits[(size_t)(t0 + ty*8 + j) * NE + tx] = acc[j];
}

__global__ void zero_cnt() { if (threadIdx.x < NE) g_cnt[threadIdx.x] = 0; }

__global__ void topk_kernel(const float* __restrict__ logits) {
    int t = blockIdx.x * blockDim.x + threadIdx.x;
    if (t >= T_TOK) return;
    float v[NE];
#pragma unroll
    for (int e = 0; e < NE; e++) v[e] = logits[(size_t)t * NE + e];
    float val[TOPK]; int sel[TOPK];
#pragma unroll
    for (int kk = 0; kk < TOPK; kk++) {
        float best = -INFINITY; int bi = 0;
#pragma unroll
        for (int e = 0; e < NE; e++)
            if (v[e] > best) { best = v[e]; bi = e; }
        val[kk] = best; sel[kk] = bi; v[bi] = -INFINITY;
    }
    float mx = val[0];
    float w[TOPK], s = 0.f;
#pragma unroll
    for (int kk = 0; kk < TOPK; kk++) { w[kk] = expf(val[kk] - mx); s += w[kk]; }
    float inv = 1.f / s;
#pragma unroll
    for (int kk = 0; kk < TOPK; kk++) {
        int e = sel[kk];
        int pos = atomicAdd(&g_cnt[e], 1);
        g_btok[e * T_TOK + pos] = t;
        g_bw  [e * T_TOK + pos] = w[kk] * inv;
        g_pe[t * TOPK + kk] = e;
        g_pp[t * TOPK + kk] = pos;
    }
}

__global__ void prefix_kernel() {
    if (threadIdx.x == 0) {
        int s = 0;
        for (int e = 0; e < NE; e++) { g_base[e] = s; s += g_cnt[e]; }
    }
}

// ================= gate/up HMMA kernel (fp16 1-pass, pipelined) =================
// CTA: 128 tokens x 64 F-cols, 8 warps, BK=32, X cp.async 2-stage, W reg-prefetch.
// SMEM: X stage s at s*10240 (128 rows x 80B); W at 20480 { Gh +0, Uh +5120 }. Total 30720.
#define PADK 40
#define XSTG 10240
#define GU_SMEM 30720
#define DN_SMEM 30720
__global__ void __launch_bounds__(256, 2) gateup_mma(
        const float* __restrict__ wg, const float* __restrict__ wu) {
    int e   = blockIdx.z;
    int cnt = g_cnt[e];
    int m0  = blockIdx.y * 128;
    if (m0 >= cnt) return;
    int f0 = blockIdx.x * 64;

    extern __shared__ __align__(128) char smem[];
    uint32_t sb = smem_u32(smem);

    int tid = threadIdx.x, wid = tid >> 5, lane = tid & 31;
    int wm = wid & 3, wn = wid >> 2;
    int g = lane >> 2, q = lane & 3;

    // X loader: 128 rows, 2 threads/row, 16 halfs each (32B)
    int xrow = tid >> 1, xhalf = tid & 1;
    int tokL = g_btok[e * T_TOK + min(m0 + xrow, cnt - 1)];
    const __half* xs = g_x16 + (size_t)tokL * HDIM + xhalf * 16;
    uint32_t xdst = sb + (uint32_t)xrow * 80 + (uint32_t)xhalf * 32;

    // W loader: 64 rows x 4 segs of 8 fp32
    int wrow = tid >> 2, wq = tid & 3;
    const float* gsrc = wg + (size_t)e * FDIM * HDIM + (size_t)(f0 + wrow) * HDIM + wq * 8;
    const float* usrc = wu + (size_t)e * FDIM * HDIM + (size_t)(f0 + wrow) * HDIM + wq * 8;
    char* wbase = smem + 20480 + wrow * 80 + wq * 16;

    float accG[2][4][4] = {}, accU[2][4][4] = {};

    const int NC = HDIM / 32;
    float gcur[8], ucur[8];
    *(float4*)&gcur[0] = *(const float4*)(gsrc);
    *(float4*)&gcur[4] = *(const float4*)(gsrc + 4);
    *(float4*)&ucur[0] = *(const float4*)(usrc);
    *(float4*)&ucur[4] = *(const float4*)(usrc + 4);
    cpa16(xdst, xs); cpa16(xdst + 16, xs + 8);
    CP_COMMIT();

    for (int ci = 0; ci < NC; ci++) {
        // convert+store W(ci) (safe: trailing sync of prev iter)
        {
            uint4 hv;
            cvt8h(gcur, hv); *(uint4*)(wbase)        = hv;
            cvt8h(ucur, hv); *(uint4*)(wbase + 5120) = hv;
        }
        float gn[8], un[8];
        if (ci + 1 < NC) {
            int kk = (ci + 1) * 32;
            uint32_t so = ((ci + 1) & 1) * XSTG;
            cpa16(xdst + so, xs + kk); cpa16(xdst + so + 16, xs + kk + 8);
            CP_COMMIT();
            *(float4*)&gn[0] = *(const float4*)(gsrc + kk);
            *(float4*)&gn[4] = *(const float4*)(gsrc + kk + 4);
            *(float4*)&un[0] = *(const float4*)(usrc + kk);
            *(float4*)&un[4] = *(const float4*)(usrc + kk + 4);
            cp_wait<1>();
        } else {
            cp_wait<0>();
        }
        __syncthreads();

        const __half* sX  = (const __half*)(smem + (ci & 1) * XSTG);
        const __half* sGh = (const __half*)(smem + 20480);
        const __half* sUh = (const __half*)(smem + 20480 + 5120);

#pragma unroll
        for (int kt = 0; kt < 2; kt++) {
            int kc = kt * 16 + 2 * q;
            uint32_t ax[2][4];
#pragma unroll
            for (int mt = 0; mt < 2; mt++) {
                int r = wm * 32 + mt * 16 + g;
                ax[mt][0] = *(const uint32_t*)&sX[r*PADK + kc];
                ax[mt][1] = *(const uint32_t*)&sX[(r+8)*PADK + kc];
                ax[mt][2] = *(const uint32_t*)&sX[r*PADK + kc + 8];
                ax[mt][3] = *(const uint32_t*)&sX[(r+8)*PADK + kc + 8];
            }
#pragma unroll
            for (int nt = 0; nt < 4; nt++) {
                int br = wn * 32 + nt * 8 + g;
                uint32_t bgh[2] = {*(const uint32_t*)&sGh[br*PADK + kc], *(const uint32_t*)&sGh[br*PADK + kc + 8]};
                uint32_t buh[2] = {*(const uint32_t*)&sUh[br*PADK + kc], *(const uint32_t*)&sUh[br*PADK + kc + 8]};
#pragma unroll
                for (int mt = 0; mt < 2; mt++) {
                    mma16816h(accG[mt][nt], ax[mt], bgh);
                    mma16816h(accU[mt][nt], ax[mt], buh);
                }
            }
        }
        __syncthreads();
        if (ci + 1 < NC) {
#pragma unroll
            for (int i = 0; i < 8; i++) { gcur[i] = gn[i]; ucur[i] = un[i]; }
        }
    }

    // epilogue: h = relu(G)*U -> fp16
    int base = g_base[e];
#pragma unroll
    for (int mt = 0; mt < 2; mt++) {
        int lm0 = wm * 32 + mt * 16 + g;
#pragma unroll
        for (int nt = 0; nt < 4; nt++) {
            int c = f0 + wn * 32 + nt * 8 + 2 * q;
            float* Gd = accG[mt][nt];
            float* Ud = accU[mt][nt];
            float v0 = fmaxf(Gd[0], 0.f) * Ud[0];
            float v1 = fmaxf(Gd[1], 0.f) * Ud[1];
            float v2 = fmaxf(Gd[2], 0.f) * Ud[2];
            float v3 = fmaxf(Gd[3], 0.f) * Ud[3];
            __half2 h01 = __floats2half2_rn(v0, v1);
            __half2 h23 = __floats2half2_rn(v2, v3);
            int m = m0 + lm0;
            if (m < cnt)
                *(__half2*)(g_h + ((size_t)base + m) * FDIM + c) = h01;
            if (m + 8 < cnt)
                *(__half2*)(g_h + ((size_t)base + m + 8) * FDIM + c) = h23;
        }
    }
}

// ================= down HMMA kernel (fp16 1-pass, BN=128, pipelined) =================
// SMEM: X stage s at s*10240; W at 20480 (128 rows x 80B single buffer). Total 30720.
__global__ void __launch_bounds__(256, 2) down_mma(const float* __restrict__ wd) {
    int e   = blockIdx.z;
    int cnt = g_cnt[e];
    int m0  = blockIdx.y * 128;
    if (m0 >= cnt) return;
    int h0 = blockIdx.x * 128;

    extern __shared__ __align__(128) char smem[];
    uint32_t sb = smem_u32(smem);

    int tid = threadIdx.x, wid = tid >> 5, lane = tid & 31;
    int wm = wid & 3, wn = wid >> 2;
    int g = lane >> 2, q = lane & 3;
    int base = g_base[e];

    int xrow = tid >> 1, xhalf = tid & 1;
    size_t slotR = (size_t)base + min(m0 + xrow, cnt - 1);
    const __half* xs = g_h + slotR * FDIM + xhalf * 16;
    uint32_t xdst = sb + (uint32_t)xrow * 80 + (uint32_t)xhalf * 32;

    // W loader: 128 rows, 2 threads/row, 16 fp32 each
    int wrow = tid >> 1, wseg = tid & 1;
    const float* wsrc = wd + (size_t)e * HDIM * FDIM + (size_t)(h0 + wrow) * FDIM + wseg * 16;
    char* wbase = smem + 20480 + wrow * 80 + wseg * 32;

    float acc[2][8][4] = {};

    const int NC = FDIM / 32;
    float wcur[16];
    *(float4*)&wcur[0]  = *(const float4*)(wsrc);
    *(float4*)&wcur[4]  = *(const float4*)(wsrc + 4);
    *(float4*)&wcur[8]  = *(const float4*)(wsrc + 8);
    *(float4*)&wcur[12] = *(const float4*)(wsrc + 12);
    cpa16(xdst, xs); cpa16(xdst + 16, xs + 8);
    CP_COMMIT();

    for (int ci = 0; ci < NC; ci++) {
        {
            uint4 hv;
            cvt8h(wcur, hv);     *(uint4*)(wbase)      = hv;
            cvt8h(wcur + 8, hv); *(uint4*)(wbase + 16) = hv;
        }
        float wn16[16];
        if (ci + 1 < NC) {
            int kk = (ci + 1) * 32;
            uint32_t so = ((ci + 1) & 1) * XSTG;
            cpa16(xdst + so, xs + kk); cpa16(xdst + so + 16, xs + kk + 8);
            CP_COMMIT();
            *(float4*)&wn16[0]  = *(const float4*)(wsrc + kk);
            *(float4*)&wn16[4]  = *(const float4*)(wsrc + kk + 4);
            *(float4*)&wn16[8]  = *(const float4*)(wsrc + kk + 8);
            *(float4*)&wn16[12] = *(const float4*)(wsrc + kk + 12);
            cp_wait<1>();
        } else {
            cp_wait<0>();
        }
        __syncthreads();

        const __half* sX = (const __half*)(smem + (ci & 1) * XSTG);
        const __half* sW = (const __half*)(smem + 20480);

#pragma unroll
        for (int kt = 0; kt < 2; kt++) {
            int kc = kt * 16 + 2 * q;
            uint32_t ax[2][4];
#pragma unroll
            for (int mt = 0; mt < 2; mt++) {
                int r = wm * 32 + mt * 16 + g;
                ax[mt][0] = *(const uint32_t*)&sX[r*PADK + kc];
                ax[mt][1] = *(const uint32_t*)&sX[(r+8)*PADK + kc];
                ax[mt][2] = *(const uint32_t*)&sX[r*PADK + kc + 8];
                ax[mt][3] = *(const uint32_t*)&sX[(r+8)*PADK + kc + 8];
            }
#pragma unroll
            for (int nt = 0; nt < 8; nt++) {
                int br = wn * 64 + nt * 8 + g;
                uint32_t bw[2] = {*(const uint32_t*)&sW[br*PADK + kc], *(const uint32_t*)&sW[br*PADK + kc + 8]};
#pragma unroll
                for (int mt = 0; mt < 2; mt++)
                    mma16816h(acc[mt][nt], ax[mt], bw);
            }
        }
        __syncthreads();
        if (ci + 1 < NC) {
#pragma unroll
            for (int i = 0; i < 16; i++) wcur[i] = wn16[i];
        }
    }

    // epilogue: y = acc * routing weight
#pragma unroll
    for (int mt = 0; mt < 2; mt++) {
        int lm0 = wm * 32 + mt * 16 + g;
        int m = m0 + lm0;
        float w0 = (m     < cnt) ? g_bw[e * T_TOK + m]     : 0.f;
        float w1 = (m + 8 < cnt) ? g_bw[e * T_TOK + m + 8] : 0.f;
#pragma unroll
        for (int nt = 0; nt < 8; nt++) {
            int c = h0 + wn * 64 + nt * 8 + 2 * q;
            float* D = acc[mt][nt];
            if (m < cnt) {
                float* py = g_ybuf + ((size_t)base + m) * HDIM + c;
                py[0] = D[0] * w0; py[1] = D[1] * w0;
            }
            if (m + 8 < cnt) {
                float* py = g_ybuf + ((size_t)base + m + 8) * HDIM + c;
                py[0] = D[2] * w1; py[1] = D[3] * w1;
            }
        }
    }
}

// ---------------- combine ----------------
__global__ void combine_kernel(float* __restrict__ out) {
    int t   = blockIdx.x;
    int tid = threadIdx.x;
    int sl[TOPK];
#pragma unroll
    for (int kk = 0; kk < TOPK; kk++)
        sl[kk] = g_base[g_pe[t*TOPK + kk]] + g_pp[t*TOPK + kk];
    int h = tid * 4;
    float4 a = *(const float4*)(g_ybuf + (size_t)sl[0] * HDIM + h);
    float4 b = *(const float4*)(g_ybuf + (size_t)sl[1] * HDIM + h);
    float4 c = *(const float4*)(g_ybuf + (size_t)sl[2] * HDIM + h);
    float4 d = *(const float4*)(g_ybuf + (size_t)sl[3] * HDIM + h);
    float4 r;
    r.x = a.x + b.x + c.x + d.x;
    r.y = a.y + b.y + c.y + d.y;
    r.z = a.z + b.z + c.z + d.z;
    r.w = a.w + b.w + c.w + d.w;
    *(float4*)(out + (size_t)t * HDIM + h) = r;
}

// ---------------- launch ----------------
extern "C" void kernel_launch(void* const* d_in, const int* in_sizes, int n_in,
                              void* d_out, int out_size) {
    const float* router_input = (const float*)d_in[0];
    const float* hidden       = (const float*)d_in[1];
    const float* w_router     = (const float*)d_in[2];
    const float* w_gate       = (const float*)d_in[3];
    const float* w_up         = (const float*)d_in[4];
    const float* w_down       = (const float*)d_in[5];
    float* out    = (float*)d_out;
    float* logits = out + (size_t)T_TOK * HDIM;

    static int attr_done = 0;
    if (!attr_done) {
        cudaFuncSetAttribute(gateup_mma, cudaFuncAttributeMaxDynamicSharedMemorySize, GU_SMEM);
        cudaFuncSetAttribute(down_mma,   cudaFuncAttributeMaxDynamicSharedMemorySize, DN_SMEM);
        attr_done = 1;
    }

    __half *x16;
    cudaGetSymbolAddress((void**)&x16, g_x16);

    const int XN8 = T_TOK * HDIM / 8;
    convert_f16<<<XN8 / 256, 256>>>(hidden, x16, XN8);

    zero_cnt<<<1, 32>>>();
    router_gemm<<<T_TOK / 64, 256>>>(router_input, w_router, logits);
    topk_kernel<<<T_TOK / 256, 256>>>(logits);
    prefix_kernel<<<1, 32>>>();
    gateup_mma<<<dim3(FDIM / 64, T_TOK / 128, NE), 256, GU_SMEM>>>(w_gate, w_up);
    down_mma<<<dim3(HDIM / 128, T_TOK / 128, NE), 256, DN_SMEM>>>(w_down);
    combine_kernel<<<T_TOK, 256>>>(out);
}

// round 15
// speedup vs baseline: 1.9012x; 1.1981x over previous
#include <cuda_runtime.h>
#include <cuda_fp16.h>
#include <math.h>
#include <stdint.h>

#define T_TOK 2048
#define HDIM  1024
#define FDIM  512
#define NE    32
#define TOPK  4
#define SLOTS (T_TOK * TOPK)

// ---------------- scratch ----------------
__device__ int   g_cnt[NE];
__device__ int   g_base[NE];
__device__ int   g_btok[NE * T_TOK];
__device__ float g_bw  [NE * T_TOK];
__device__ int   g_pe  [T_TOK * TOPK];
__device__ int   g_pp  [T_TOK * TOPK];
__device__ __half g_h  [(size_t)SLOTS * FDIM];   // 8 MB
__device__ float  g_ybuf[(size_t)SLOTS * HDIM];  // 32 MB
__device__ __half g_x16[(size_t)T_TOK * HDIM];   // 4 MB

// ---------------- helpers ----------------
__device__ __forceinline__ void mma16816h(float* d, const uint32_t* a, const uint32_t* b) {
    asm volatile(
        "mma.sync.aligned.m16n8k16.row.col.f32.f16.f16.f32 "
        "{%0,%1,%2,%3}, {%4,%5,%6,%7}, {%8,%9}, {%0,%1,%2,%3};\n"
        : "+f"(d[0]), "+f"(d[1]), "+f"(d[2]), "+f"(d[3])
        : "r"(a[0]), "r"(a[1]), "r"(a[2]), "r"(a[3]), "r"(b[0]), "r"(b[1]));
}

__device__ __forceinline__ uint32_t smem_u32(const void* p) {
    uint32_t a;
    asm("{ .reg .u64 t; cvta.to.shared.u64 t, %1; cvt.u32.u64 %0, t; }" : "=r"(a) : "l"(p));
    return a;
}
__device__ __forceinline__ void cpa16(uint32_t dst, const void* src) {
    asm volatile("cp.async.cg.shared.global [%0], [%1], 16;" :: "r"(dst), "l"(src));
}
#define CP_COMMIT() asm volatile("cp.async.commit_group;" ::: "memory")
template<int N> __device__ __forceinline__ void cp_wait() {
    asm volatile("cp.async.wait_group %0;" :: "n"(N) : "memory");
}

__device__ __forceinline__ void cvt8h(const float* x, uint4& hv) {
    uint32_t h[4];
#pragma unroll
    for (int i = 0; i < 4; i++) {
        __half2 hh = __floats2half2_rn(x[2*i], x[2*i+1]);
        h[i] = *reinterpret_cast<uint32_t*>(&hh);
    }
    hv = make_uint4(h[0], h[1], h[2], h[3]);
}

// ---------------- X conversion ----------------
__global__ void convert_f16(const float* __restrict__ src,
                            __half* __restrict__ dst, int n8) {
    int i = blockIdx.x * blockDim.x + threadIdx.x;
    if (i >= n8) return;
    float x[8];
    *(float4*)&x[0] = *(const float4*)(src + 8*(size_t)i);
    *(float4*)&x[4] = *(const float4*)(src + 8*(size_t)i + 4);
    uint4 hv; cvt8h(x, hv);
    *(uint4*)(dst + 8*(size_t)i) = hv;
}

// ---------------- router GEMM ----------------
__global__ void router_gemm(const float* __restrict__ xr, const float* __restrict__ wr,
                            float* __restrict__ logits) {
    __shared__ float Xs[16][68];
    __shared__ float Ws[16][36];
    int tid = threadIdx.x;
    int t0  = blockIdx.x * 64;
    int tx = tid & 31, ty = tid >> 5;
    float acc[8];
#pragma unroll
    for (int j = 0; j < 8; j++) acc[j] = 0.f;
    int mL = tid >> 2, ksL = tid & 3;
    for (int k0 = 0; k0 < HDIM; k0 += 16) {
        float4 v = *(const float4*)(xr + (size_t)(t0 + mL) * HDIM + k0 + ksL * 4);
        Xs[ksL*4+0][mL] = v.x; Xs[ksL*4+1][mL] = v.y;
        Xs[ksL*4+2][mL] = v.z; Xs[ksL*4+3][mL] = v.w;
        if (tid < 128) {
            int n = tid >> 2, ks = tid & 3;
            float4 w = *(const float4*)(wr + (size_t)n * HDIM + k0 + ks * 4);
            Ws[ks*4+0][n] = w.x; Ws[ks*4+1][n] = w.y;
            Ws[ks*4+2][n] = w.z; Ws[ks*4+3][n] = w.w;
        }
        __syncthreads();
#pragma unroll
        for (int kk = 0; kk < 16; kk++) {
            float b = Ws[kk][tx];
            float4 a0 = *(const float4*)&Xs[kk][ty*8];
            float4 a1 = *(const float4*)&Xs[kk][ty*8+4];
            acc[0] += a0.x*b; acc[1] += a0.y*b; acc[2] += a0.z*b; acc[3] += a0.w*b;
            acc[4] += a1.x*b; acc[5] += a1.y*b; acc[6] += a1.z*b; acc[7] += a1.w*b;
        }
        __syncthreads();
    }
#pragma unroll
    for (int j = 0; j < 8; j++)
        logits[(size_t)(t0 + ty*8 + j) * NE + tx] = acc[j];
}

__global__ void zero_cnt() { if (threadIdx.x < NE) g_cnt[threadIdx.x] = 0; }

__global__ void topk_kernel(const float* __restrict__ logits) {
    int t = blockIdx.x * blockDim.x + threadIdx.x;
    if (t >= T_TOK) return;
    float v[NE];
#pragma unroll
    for (int e = 0; e < NE; e++) v[e] = logits[(size_t)t * NE + e];
    float val[TOPK]; int sel[TOPK];
#pragma unroll
    for (int kk = 0; kk < TOPK; kk++) {
        float best = -INFINITY; int bi = 0;
#pragma unroll
        for (int e = 0; e < NE; e++)
            if (v[e] > best) { best = v[e]; bi = e; }
        val[kk] = best; sel[kk] = bi; v[bi] = -INFINITY;
    }
    float mx = val[0];
    float w[TOPK], s = 0.f;
#pragma unroll
    for (int kk = 0; kk < TOPK; kk++) { w[kk] = expf(val[kk] - mx); s += w[kk]; }
    float inv = 1.f / s;
#pragma unroll
    for (int kk = 0; kk < TOPK; kk++) {
        int e = sel[kk];
        int pos = atomicAdd(&g_cnt[e], 1);
        g_btok[e * T_TOK + pos] = t;
        g_bw  [e * T_TOK + pos] = w[kk] * inv;
        g_pe[t * TOPK + kk] = e;
        g_pp[t * TOPK + kk] = pos;
    }
}

__global__ void prefix_kernel() {
    if (threadIdx.x == 0) {
        int s = 0;
        for (int e = 0; e < NE; e++) { g_base[e] = s; s += g_cnt[e]; }
    }
}

// ================= gate/up HMMA kernel (fp16 1-pass, single-sync pipeline) =================
// CTA: 128 tokens x 64 F-cols, 8 warps, BK=32.
// SMEM: X stage s at s*10240 (128 x 80B); W stage s at 20480 + s*10240 { Gh +0, Uh +5120 }.
// Total 40960. One __syncthreads per chunk.
#define PADK 40
#define XSTG 10240
#define WOFF 20480
#define WSTG 10240
#define GU_SMEM 40960
#define DN_SMEM 40960
__global__ void __launch_bounds__(256, 2) gateup_mma(
        const float* __restrict__ wg, const float* __restrict__ wu) {
    int e   = blockIdx.z;
    int cnt = g_cnt[e];
    int m0  = blockIdx.y * 128;
    if (m0 >= cnt) return;
    int f0 = blockIdx.x * 64;

    extern __shared__ __align__(128) char smem[];
    uint32_t sb = smem_u32(smem);

    int tid = threadIdx.x, wid = tid >> 5, lane = tid & 31;
    int wm = wid & 3, wn = wid >> 2;
    int g = lane >> 2, q = lane & 3;

    // X loader: 128 rows, 2 threads/row, 16 halfs each
    int xrow = tid >> 1, xhalf = tid & 1;
    int tokL = g_btok[e * T_TOK + min(m0 + xrow, cnt - 1)];
    const __half* xs = g_x16 + (size_t)tokL * HDIM + xhalf * 16;
    uint32_t xdst = sb + (uint32_t)xrow * 80 + (uint32_t)xhalf * 32;

    // W loader: 64 rows x 4 segs of 8 fp32
    int wrow = tid >> 2, wq = tid & 3;
    const float* gsrc = wg + (size_t)e * FDIM * HDIM + (size_t)(f0 + wrow) * HDIM + wq * 8;
    const float* usrc = wu + (size_t)e * FDIM * HDIM + (size_t)(f0 + wrow) * HDIM + wq * 8;
    uint32_t wdoff = WOFF + (uint32_t)wrow * 80 + (uint32_t)wq * 16;

    float accG[2][4][4] = {}, accU[2][4][4] = {};

    const int NC = HDIM / 32;
    // prologue: W(0) -> regs -> smem stage0; X(0) cp.async stage0; prefetch W(1) regs
    float gcur[8], ucur[8];
    {
        float r[8]; uint4 hv;
        *(float4*)&r[0] = *(const float4*)(gsrc);
        *(float4*)&r[4] = *(const float4*)(gsrc + 4);
        cvt8h(r, hv); *(uint4*)(smem + wdoff)        = hv;
        *(float4*)&r[0] = *(const float4*)(usrc);
        *(float4*)&r[4] = *(const float4*)(usrc + 4);
        cvt8h(r, hv); *(uint4*)(smem + wdoff + 5120) = hv;
    }
    cpa16(xdst, xs); cpa16(xdst + 16, xs + 8);
    CP_COMMIT();
    *(float4*)&gcur[0] = *(const float4*)(gsrc + 32);
    *(float4*)&gcur[4] = *(const float4*)(gsrc + 36);
    *(float4*)&ucur[0] = *(const float4*)(usrc + 32);
    *(float4*)&ucur[4] = *(const float4*)(usrc + 36);
    cp_wait<0>();
    __syncthreads();

    for (int ci = 0; ci < NC; ci++) {
        // issue X(ci+1) into the other stage (free: its readers finished at last sync)
        if (ci + 1 < NC) {
            int kk = (ci + 1) * 32;
            uint32_t so = ((ci + 1) & 1) * XSTG;
            cpa16(xdst + so, xs + kk); cpa16(xdst + so + 16, xs + kk + 8);
            CP_COMMIT();
        }

        const __half* sX  = (const __half*)(smem + (ci & 1) * XSTG);
        const __half* sGh = (const __half*)(smem + WOFF + (ci & 1) * WSTG);
        const __half* sUh = (const __half*)(smem + WOFF + (ci & 1) * WSTG + 5120);

#pragma unroll
        for (int kt = 0; kt < 2; kt++) {
            int kc = kt * 16 + 2 * q;
            uint32_t ax[2][4];
#pragma unroll
            for (int mt = 0; mt < 2; mt++) {
                int r = wm * 32 + mt * 16 + g;
                ax[mt][0] = *(const uint32_t*)&sX[r*PADK + kc];
                ax[mt][1] = *(const uint32_t*)&sX[(r+8)*PADK + kc];
                ax[mt][2] = *(const uint32_t*)&sX[r*PADK + kc + 8];
                ax[mt][3] = *(const uint32_t*)&sX[(r+8)*PADK + kc + 8];
            }
#pragma unroll
            for (int nt = 0; nt < 4; nt++) {
                int br = wn * 32 + nt * 8 + g;
                uint32_t bgh[2] = {*(const uint32_t*)&sGh[br*PADK + kc], *(const uint32_t*)&sGh[br*PADK + kc + 8]};
                uint32_t buh[2] = {*(const uint32_t*)&sUh[br*PADK + kc], *(const uint32_t*)&sUh[br*PADK + kc + 8]};
#pragma unroll
                for (int mt = 0; mt < 2; mt++) {
                    mma16816h(accG[mt][nt], ax[mt], bgh);
                    mma16816h(accU[mt][nt], ax[mt], buh);
                }
            }
        }

        if (ci + 1 < NC) {
            // store W(ci+1) into the other W stage (no reader conflict)
            uint32_t wo = wdoff + ((ci + 1) & 1) * WSTG;
            uint4 hv;
            cvt8h(gcur, hv); *(uint4*)(smem + wo)        = hv;
            cvt8h(ucur, hv); *(uint4*)(smem + wo + 5120) = hv;
            if (ci + 2 < NC) {
                int kk = (ci + 2) * 32;
                *(float4*)&gcur[0] = *(const float4*)(gsrc + kk);
                *(float4*)&gcur[4] = *(const float4*)(gsrc + kk + 4);
                *(float4*)&ucur[0] = *(const float4*)(usrc + kk);
                *(float4*)&ucur[4] = *(const float4*)(usrc + kk + 4);
            }
            cp_wait<0>();
        }
        __syncthreads();
    }

    // epilogue: h = relu(G)*U -> fp16
    int base = g_base[e];
#pragma unroll
    for (int mt = 0; mt < 2; mt++) {
        int lm0 = wm * 32 + mt * 16 + g;
#pragma unroll
        for (int nt = 0; nt < 4; nt++) {
            int c = f0 + wn * 32 + nt * 8 + 2 * q;
            float* Gd = accG[mt][nt];
            float* Ud = accU[mt][nt];
            float v0 = fmaxf(Gd[0], 0.f) * Ud[0];
            float v1 = fmaxf(Gd[1], 0.f) * Ud[1];
            float v2 = fmaxf(Gd[2], 0.f) * Ud[2];
            float v3 = fmaxf(Gd[3], 0.f) * Ud[3];
            __half2 h01 = __floats2half2_rn(v0, v1);
            __half2 h23 = __floats2half2_rn(v2, v3);
            int m = m0 + lm0;
            if (m < cnt)
                *(__half2*)(g_h + ((size_t)base + m) * FDIM + c) = h01;
            if (m + 8 < cnt)
                *(__half2*)(g_h + ((size_t)base + m + 8) * FDIM + c) = h23;
        }
    }
}

// ================= down HMMA kernel (fp16 1-pass, BN=128, single-sync pipeline) =================
// SMEM: X stage s at s*10240; W stage s at 20480 + s*10240 (128 x 80B). Total 40960.
__global__ void __launch_bounds__(256, 2) down_mma(const float* __restrict__ wd) {
    int e   = blockIdx.z;
    int cnt = g_cnt[e];
    int m0  = blockIdx.y * 128;
    if (m0 >= cnt) return;
    int h0 = blockIdx.x * 128;

    extern __shared__ __align__(128) char smem[];
    uint32_t sb = smem_u32(smem);

    int tid = threadIdx.x, wid = tid >> 5, lane = tid & 31;
    int wm = wid & 3, wn = wid >> 2;
    int g = lane >> 2, q = lane & 3;
    int base = g_base[e];

    int xrow = tid >> 1, xhalf = tid & 1;
    size_t slotR = (size_t)base + min(m0 + xrow, cnt - 1);
    const __half* xs = g_h + slotR * FDIM + xhalf * 16;
    uint32_t xdst = sb + (uint32_t)xrow * 80 + (uint32_t)xhalf * 32;

    // W loader: 128 rows, 2 threads/row, 16 fp32 each
    int wrow = tid >> 1, wseg = tid & 1;
    const float* wsrc = wd + (size_t)e * HDIM * FDIM + (size_t)(h0 + wrow) * FDIM + wseg * 16;
    uint32_t wdoff = WOFF + (uint32_t)wrow * 80 + (uint32_t)wseg * 32;

    float acc[2][8][4] = {};

    const int NC = FDIM / 32;
    float wcur[16];
    {
        float r[16]; uint4 hv;
        *(float4*)&r[0]  = *(const float4*)(wsrc);
        *(float4*)&r[4]  = *(const float4*)(wsrc + 4);
        *(float4*)&r[8]  = *(const float4*)(wsrc + 8);
        *(float4*)&r[12] = *(const float4*)(wsrc + 12);
        cvt8h(r, hv);     *(uint4*)(smem + wdoff)      = hv;
        cvt8h(r + 8, hv); *(uint4*)(smem + wdoff + 16) = hv;
    }
    cpa16(xdst, xs); cpa16(xdst + 16, xs + 8);
    CP_COMMIT();
    *(float4*)&wcur[0]  = *(const float4*)(wsrc + 32);
    *(float4*)&wcur[4]  = *(const float4*)(wsrc + 36);
    *(float4*)&wcur[8]  = *(const float4*)(wsrc + 40);
    *(float4*)&wcur[12] = *(const float4*)(wsrc + 44);
    cp_wait<0>();
    __syncthreads();

    for (int ci = 0; ci < NC; ci++) {
        if (ci + 1 < NC) {
            int kk = (ci + 1) * 32;
            uint32_t so = ((ci + 1) & 1) * XSTG;
            cpa16(xdst + so, xs + kk); cpa16(xdst + so + 16, xs + kk + 8);
            CP_COMMIT();
        }

        const __half* sX = (const __half*)(smem + (ci & 1) * XSTG);
        const __half* sW = (const __half*)(smem + WOFF + (ci & 1) * WSTG);

#pragma unroll
        for (int kt = 0; kt < 2; kt++) {
            int kc = kt * 16 + 2 * q;
            uint32_t ax[2][4];
#pragma unroll
            for (int mt = 0; mt < 2; mt++) {
                int r = wm * 32 + mt * 16 + g;
                ax[mt][0] = *(const uint32_t*)&sX[r*PADK + kc];
                ax[mt][1] = *(const uint32_t*)&sX[(r+8)*PADK + kc];
                ax[mt][2] = *(const uint32_t*)&sX[r*PADK + kc + 8];
                ax[mt][3] = *(const uint32_t*)&sX[(r+8)*PADK + kc + 8];
            }
#pragma unroll
            for (int nt = 0; nt < 8; nt++) {
                int br = wn * 64 + nt * 8 + g;
                uint32_t bw[2] = {*(const uint32_t*)&sW[br*PADK + kc], *(const uint32_t*)&sW[br*PADK + kc + 8]};
#pragma unroll
                for (int mt = 0; mt < 2; mt++)
                    mma16816h(acc[mt][nt], ax[mt], bw);
            }
        }

        if (ci + 1 < NC) {
            uint32_t wo = wdoff + ((ci + 1) & 1) * WSTG;
            uint4 hv;
            cvt8h(wcur, hv);     *(uint4*)(smem + wo)      = hv;
            cvt8h(wcur + 8, hv); *(uint4*)(smem + wo + 16) = hv;
            if (ci + 2 < NC) {
                int kk = (ci + 2) * 32;
                *(float4*)&wcur[0]  = *(const float4*)(wsrc + kk);
                *(float4*)&wcur[4]  = *(const float4*)(wsrc + kk + 4);
                *(float4*)&wcur[8]  = *(const float4*)(wsrc + kk + 8);
                *(float4*)&wcur[12] = *(const float4*)(wsrc + kk + 12);
            }
            cp_wait<0>();
        }
        __syncthreads();
    }

    // epilogue: y = acc * routing weight
#pragma unroll
    for (int mt = 0; mt < 2; mt++) {
        int lm0 = wm * 32 + mt * 16 + g;
        int m = m0 + lm0;
        float w0 = (m     < cnt) ? g_bw[e * T_TOK + m]     : 0.f;
        float w1 = (m + 8 < cnt) ? g_bw[e * T_TOK + m + 8] : 0.f;
#pragma unroll
        for (int nt = 0; nt < 8; nt++) {
            int c = h0 + wn * 64 + nt * 8 + 2 * q;
            float* D = acc[mt][nt];
            if (m < cnt) {
                float* py = g_ybuf + ((size_t)base + m) * HDIM + c;
                py[0] = D[0] * w0; py[1] = D[1] * w0;
            }
            if (m + 8 < cnt) {
                float* py = g_ybuf + ((size_t)base + m + 8) * HDIM + c;
                py[0] = D[2] * w1; py[1] = D[3] * w1;
            }
        }
    }
}

// ---------------- combine ----------------
__global__ void combine_kernel(float* __restrict__ out) {
    int t   = blockIdx.x;
    int tid = threadIdx.x;
    int sl[TOPK];
#pragma unroll
    for (int kk = 0; kk < TOPK; kk++)
        sl[kk] = g_base[g_pe[t*TOPK + kk]] + g_pp[t*TOPK + kk];
    int h = tid * 4;
    float4 a = *(const float4*)(g_ybuf + (size_t)sl[0] * HDIM + h);
    float4 b = *(const float4*)(g_ybuf + (size_t)sl[1] * HDIM + h);
    float4 c = *(const float4*)(g_ybuf + (size_t)sl[2] * HDIM + h);
    float4 d = *(const float4*)(g_ybuf + (size_t)sl[3] * HDIM + h);
    float4 r;
    r.x = a.x + b.x + c.x + d.x;
    r.y = a.y + b.y + c.y + d.y;
    r.z = a.z + b.z + c.z + d.z;
    r.w = a.w + b.w + c.w + d.w;
    *(float4*)(out + (size_t)t * HDIM + h) = r;
}

// ---------------- launch ----------------
extern "C" void kernel_launch(void* const* d_in, const int* in_sizes, int n_in,
                              void* d_out, int out_size) {
    const float* router_input = (const float*)d_in[0];
    const float* hidden       = (const float*)d_in[1];
    const float* w_router     = (const float*)d_in[2];
    const float* w_gate       = (const float*)d_in[3];
    const float* w_up         = (const float*)d_in[4];
    const float* w_down       = (const float*)d_in[5];
    float* out    = (float*)d_out;
    float* logits = out + (size_t)T_TOK * HDIM;

    static int attr_done = 0;
    if (!attr_done) {
        cudaFuncSetAttribute(gateup_mma, cudaFuncAttributeMaxDynamicSharedMemorySize, GU_SMEM);
        cudaFuncSetAttribute(down_mma,   cudaFuncAttributeMaxDynamicSharedMemorySize, DN_SMEM);
        attr_done = 1;
    }

    __half *x16;
    cudaGetSymbolAddress((void**)&x16, g_x16);

    const int XN8 = T_TOK * HDIM / 8;
    convert_f16<<<XN8 / 256, 256>>>(hidden, x16, XN8);

    zero_cnt<<<1, 32>>>();
    router_gemm<<<T_TOK / 64, 256>>>(router_input, w_router, logits);
    topk_kernel<<<T_TOK / 256, 256>>>(logits);
    prefix_kernel<<<1, 32>>>();
    gateup_mma<<<dim3(FDIM / 64, T_TOK / 128, NE), 256, GU_SMEM>>>(w_gate, w_up);
    down_mma<<<dim3(HDIM / 128, T_TOK / 128, NE), 256, DN_SMEM>>>(w_down);
    combine_kernel<<<T_TOK, 256>>>(out);
}

// round 16
// speedup vs baseline: 1.9304x; 1.0154x over previous
#include <cuda_runtime.h>
#include <cuda_fp16.h>
#include <math.h>
#include <stdint.h>

#define T_TOK 2048
#define HDIM  1024
#define FDIM  512
#define NE    32
#define TOPK  4
#define SLOTS (T_TOK * TOPK)

// ---------------- scratch ----------------
__device__ int   g_cnt[NE];
__device__ int   g_base[NE];
__device__ int   g_btok[NE * T_TOK];
__device__ float g_bw  [NE * T_TOK];
__device__ int   g_pe  [T_TOK * TOPK];
__device__ int   g_pp  [T_TOK * TOPK];
__device__ __half g_h  [(size_t)SLOTS * FDIM];   // 8 MB
__device__ __half g_y  [(size_t)SLOTS * HDIM];   // 16 MB (fp16 y)
__device__ __half g_x16[(size_t)T_TOK * HDIM];   // 4 MB

// ---------------- helpers ----------------
__device__ __forceinline__ void mma16816h(float* d, const uint32_t* a, const uint32_t* b) {
    asm volatile(
        "mma.sync.aligned.m16n8k16.row.col.f32.f16.f16.f32 "
        "{%0,%1,%2,%3}, {%4,%5,%6,%7}, {%8,%9}, {%0,%1,%2,%3};\n"
        : "+f"(d[0]), "+f"(d[1]), "+f"(d[2]), "+f"(d[3])
        : "r"(a[0]), "r"(a[1]), "r"(a[2]), "r"(a[3]), "r"(b[0]), "r"(b[1]));
}

__device__ __forceinline__ uint32_t smem_u32(const void* p) {
    uint32_t a;
    asm("{ .reg .u64 t; cvta.to.shared.u64 t, %1; cvt.u32.u64 %0, t; }" : "=r"(a) : "l"(p));
    return a;
}
__device__ __forceinline__ void cpa16(uint32_t dst, const void* src) {
    asm volatile("cp.async.cg.shared.global [%0], [%1], 16;" :: "r"(dst), "l"(src));
}
#define CP_COMMIT() asm volatile("cp.async.commit_group;" ::: "memory")
template<int N> __device__ __forceinline__ void cp_wait() {
    asm volatile("cp.async.wait_group %0;" :: "n"(N) : "memory");
}

__device__ __forceinline__ void cvt8h(const float* x, uint4& hv) {
    uint32_t h[4];
#pragma unroll
    for (int i = 0; i < 4; i++) {
        __half2 hh = __floats2half2_rn(x[2*i], x[2*i+1]);
        h[i] = *reinterpret_cast<uint32_t*>(&hh);
    }
    hv = make_uint4(h[0], h[1], h[2], h[3]);
}

// ---------------- X conversion ----------------
__global__ void convert_f16(const float* __restrict__ src,
                            __half* __restrict__ dst, int n8) {
    int i = blockIdx.x * blockDim.x + threadIdx.x;
    if (i >= n8) return;
    float x[8];
    *(float4*)&x[0] = *(const float4*)(src + 8*(size_t)i);
    *(float4*)&x[4] = *(const float4*)(src + 8*(size_t)i + 4);
    uint4 hv; cvt8h(x, hv);
    *(uint4*)(dst + 8*(size_t)i) = hv;
}

// ---------------- router GEMM ----------------
__global__ void router_gemm(const float* __restrict__ xr, const float* __restrict__ wr,
                            float* __restrict__ logits) {
    __shared__ float Xs[16][68];
    __shared__ float Ws[16][36];
    int tid = threadIdx.x;
    int t0  = blockIdx.x * 64;
    int tx = tid & 31, ty = tid >> 5;
    float acc[8];
#pragma unroll
    for (int j = 0; j < 8; j++) acc[j] = 0.f;
    int mL = tid >> 2, ksL = tid & 3;
    for (int k0 = 0; k0 < HDIM; k0 += 16) {
        float4 v = *(const float4*)(xr + (size_t)(t0 + mL) * HDIM + k0 + ksL * 4);
        Xs[ksL*4+0][mL] = v.x; Xs[ksL*4+1][mL] = v.y;
        Xs[ksL*4+2][mL] = v.z; Xs[ksL*4+3][mL] = v.w;
        if (tid < 128) {
            int n = tid >> 2, ks = tid & 3;
            float4 w = *(const float4*)(wr + (size_t)n * HDIM + k0 + ks * 4);
            Ws[ks*4+0][n] = w.x; Ws[ks*4+1][n] = w.y;
            Ws[ks*4+2][n] = w.z; Ws[ks*4+3][n] = w.w;
        }
        __syncthreads();
#pragma unroll
        for (int kk = 0; kk < 16; kk++) {
            float b = Ws[kk][tx];
            float4 a0 = *(const float4*)&Xs[kk][ty*8];
            float4 a1 = *(const float4*)&Xs[kk][ty*8+4];
            acc[0] += a0.x*b; acc[1] += a0.y*b; acc[2] += a0.z*b; acc[3] += a0.w*b;
            acc[4] += a1.x*b; acc[5] += a1.y*b; acc[6] += a1.z*b; acc[7] += a1.w*b;
        }
        __syncthreads();
    }
#pragma unroll
    for (int j = 0; j < 8; j++)
        logits[(size_t)(t0 + ty*8 + j) * NE + tx] = acc[j];
}

__global__ void zero_cnt() { if (threadIdx.x < NE) g_cnt[threadIdx.x] = 0; }

__global__ void topk_kernel(const float* __restrict__ logits) {
    int t = blockIdx.x * blockDim.x + threadIdx.x;
    if (t >= T_TOK) return;
    float v[NE];
#pragma unroll
    for (int e = 0; e < NE; e++) v[e] = logits[(size_t)t * NE + e];
    float val[TOPK]; int sel[TOPK];
#pragma unroll
    for (int kk = 0; kk < TOPK; kk++) {
        float best = -INFINITY; int bi = 0;
#pragma unroll
        for (int e = 0; e < NE; e++)
            if (v[e] > best) { best = v[e]; bi = e; }
        val[kk] = best; sel[kk] = bi; v[bi] = -INFINITY;
    }
    float mx = val[0];
    float w[TOPK], s = 0.f;
#pragma unroll
    for (int kk = 0; kk < TOPK; kk++) { w[kk] = expf(val[kk] - mx); s += w[kk]; }
    float inv = 1.f / s;
#pragma unroll
    for (int kk = 0; kk < TOPK; kk++) {
        int e = sel[kk];
        int pos = atomicAdd(&g_cnt[e], 1);
        g_btok[e * T_TOK + pos] = t;
        g_bw  [e * T_TOK + pos] = w[kk] * inv;
        g_pe[t * TOPK + kk] = e;
        g_pp[t * TOPK + kk] = pos;
    }
}

__global__ void prefix_kernel() {
    if (threadIdx.x == 0) {
        int s = 0;
        for (int e = 0; e < NE; e++) { g_base[e] = s; s += g_cnt[e]; }
    }
}

// ================= gate/up HMMA kernel (fp16 1-pass, 3-stage X, single-sync) =================
// CTA: 128 tokens x 64 F-cols, 8 warps, BK=32.
// SMEM: X stage s at s*10240 (s=0..2, 128 x 80B); W stage s at 30720 + s*10240 { Gh +0, Uh +5120 }.
// Total 51200.
#define PADK 40
#define XSTG 10240
#define WOFF 30720
#define WSTG 10240
#define GU_SMEM 51200
#define DN_SMEM 51200
__global__ void __launch_bounds__(256, 2) gateup_mma(
        const float* __restrict__ wg, const float* __restrict__ wu) {
    int e   = blockIdx.z;
    int cnt = g_cnt[e];
    int m0  = blockIdx.y * 128;
    if (m0 >= cnt) return;
    int f0 = blockIdx.x * 64;

    extern __shared__ __align__(128) char smem[];
    uint32_t sb = smem_u32(smem);

    int tid = threadIdx.x, wid = tid >> 5, lane = tid & 31;
    int wm = wid & 3, wn = wid >> 2;
    int g = lane >> 2, q = lane & 3;

    // X loader: 128 rows, 2 threads/row, 16 halfs each
    int xrow = tid >> 1, xhalf = tid & 1;
    int tokL = g_btok[e * T_TOK + min(m0 + xrow, cnt - 1)];
    const __half* xs = g_x16 + (size_t)tokL * HDIM + xhalf * 16;
    uint32_t xdst = sb + (uint32_t)xrow * 80 + (uint32_t)xhalf * 32;

    // W loader: 64 rows x 4 segs of 8 fp32
    int wrow = tid >> 2, wq = tid & 3;
    const float* gsrc = wg + (size_t)e * FDIM * HDIM + (size_t)(f0 + wrow) * HDIM + wq * 8;
    const float* usrc = wu + (size_t)e * FDIM * HDIM + (size_t)(f0 + wrow) * HDIM + wq * 8;
    uint32_t wdoff = WOFF + (uint32_t)wrow * 80 + (uint32_t)wq * 16;

    float accG[2][4][4] = {}, accU[2][4][4] = {};

    const int NC = HDIM / 32;
    // prologue: W(0)->smem s0; X(0)->s0, X(1)->s1 in flight; W(1) regs
    float gcur[8], ucur[8];
    {
        float r[8]; uint4 hv;
        *(float4*)&r[0] = *(const float4*)(gsrc);
        *(float4*)&r[4] = *(const float4*)(gsrc + 4);
        cvt8h(r, hv); *(uint4*)(smem + wdoff)        = hv;
        *(float4*)&r[0] = *(const float4*)(usrc);
        *(float4*)&r[4] = *(const float4*)(usrc + 4);
        cvt8h(r, hv); *(uint4*)(smem + wdoff + 5120) = hv;
    }
    cpa16(xdst, xs); cpa16(xdst + 16, xs + 8);
    CP_COMMIT();
    cpa16(xdst + XSTG, xs + 32); cpa16(xdst + XSTG + 16, xs + 40);
    CP_COMMIT();
    *(float4*)&gcur[0] = *(const float4*)(gsrc + 32);
    *(float4*)&gcur[4] = *(const float4*)(gsrc + 36);
    *(float4*)&ucur[0] = *(const float4*)(usrc + 32);
    *(float4*)&ucur[4] = *(const float4*)(usrc + 36);
    cp_wait<1>();
    __syncthreads();

    for (int ci = 0; ci < NC; ci++) {
        // issue X(ci+2) into stage (ci+2)%3 (readers of that stage finished at sync end of ci-1)
        if (ci + 2 < NC) {
            int kk = (ci + 2) * 32;
            uint32_t so = (uint32_t)((ci + 2) % 3) * XSTG;
            cpa16(xdst + so, xs + kk); cpa16(xdst + so + 16, xs + kk + 8);
            CP_COMMIT();
        }

        const __half* sX  = (const __half*)(smem + (ci % 3) * XSTG);
        const __half* sGh = (const __half*)(smem + WOFF + (ci & 1) * WSTG);
        const __half* sUh = (const __half*)(smem + WOFF + (ci & 1) * WSTG + 5120);

#pragma unroll
        for (int kt = 0; kt < 2; kt++) {
            int kc = kt * 16 + 2 * q;
            uint32_t ax[2][4];
#pragma unroll
            for (int mt = 0; mt < 2; mt++) {
                int r = wm * 32 + mt * 16 + g;
                ax[mt][0] = *(const uint32_t*)&sX[r*PADK + kc];
                ax[mt][1] = *(const uint32_t*)&sX[(r+8)*PADK + kc];
                ax[mt][2] = *(const uint32_t*)&sX[r*PADK + kc + 8];
                ax[mt][3] = *(const uint32_t*)&sX[(r+8)*PADK + kc + 8];
            }
#pragma unroll
            for (int nt = 0; nt < 4; nt++) {
                int br = wn * 32 + nt * 8 + g;
                uint32_t bgh[2] = {*(const uint32_t*)&sGh[br*PADK + kc], *(const uint32_t*)&sGh[br*PADK + kc + 8]};
                uint32_t buh[2] = {*(const uint32_t*)&sUh[br*PADK + kc], *(const uint32_t*)&sUh[br*PADK + kc + 8]};
#pragma unroll
                for (int mt = 0; mt < 2; mt++) {
                    mma16816h(accG[mt][nt], ax[mt], bgh);
                    mma16816h(accU[mt][nt], ax[mt], buh);
                }
            }
        }

        if (ci + 1 < NC) {
            uint32_t wo = wdoff + ((ci + 1) & 1) * WSTG;
            uint4 hv;
            cvt8h(gcur, hv); *(uint4*)(smem + wo)        = hv;
            cvt8h(ucur, hv); *(uint4*)(smem + wo + 5120) = hv;
            if (ci + 2 < NC) {
                int kk = (ci + 2) * 32;
                *(float4*)&gcur[0] = *(const float4*)(gsrc + kk);
                *(float4*)&gcur[4] = *(const float4*)(gsrc + kk + 4);
                *(float4*)&ucur[0] = *(const float4*)(usrc + kk);
                *(float4*)&ucur[4] = *(const float4*)(usrc + kk + 4);
                cp_wait<1>();     // X(ci+1) done; X(ci+2) may fly
            } else {
                cp_wait<0>();     // only X(ci+1) pending
            }
        }
        __syncthreads();
    }

    // epilogue: h = relu(G)*U -> fp16
    int base = g_base[e];
#pragma unroll
    for (int mt = 0; mt < 2; mt++) {
        int lm0 = wm * 32 + mt * 16 + g;
#pragma unroll
        for (int nt = 0; nt < 4; nt++) {
            int c = f0 + wn * 32 + nt * 8 + 2 * q;
            float* Gd = accG[mt][nt];
            float* Ud = accU[mt][nt];
            float v0 = fmaxf(Gd[0], 0.f) * Ud[0];
            float v1 = fmaxf(Gd[1], 0.f) * Ud[1];
            float v2 = fmaxf(Gd[2], 0.f) * Ud[2];
            float v3 = fmaxf(Gd[3], 0.f) * Ud[3];
            __half2 h01 = __floats2half2_rn(v0, v1);
            __half2 h23 = __floats2half2_rn(v2, v3);
            int m = m0 + lm0;
            if (m < cnt)
                *(__half2*)(g_h + ((size_t)base + m) * FDIM + c) = h01;
            if (m + 8 < cnt)
                *(__half2*)(g_h + ((size_t)base + m + 8) * FDIM + c) = h23;
        }
    }
}

// ================= down HMMA kernel (fp16 1-pass, BN=128, 3-stage X) =================
__global__ void __launch_bounds__(256, 2) down_mma(const float* __restrict__ wd) {
    int e   = blockIdx.z;
    int cnt = g_cnt[e];
    int m0  = blockIdx.y * 128;
    if (m0 >= cnt) return;
    int h0 = blockIdx.x * 128;

    extern __shared__ __align__(128) char smem[];
    uint32_t sb = smem_u32(smem);

    int tid = threadIdx.x, wid = tid >> 5, lane = tid & 31;
    int wm = wid & 3, wn = wid >> 2;
    int g = lane >> 2, q = lane & 3;
    int base = g_base[e];

    int xrow = tid >> 1, xhalf = tid & 1;
    size_t slotR = (size_t)base + min(m0 + xrow, cnt - 1);
    const __half* xs = g_h + slotR * FDIM + xhalf * 16;
    uint32_t xdst = sb + (uint32_t)xrow * 80 + (uint32_t)xhalf * 32;

    int wrow = tid >> 1, wseg = tid & 1;
    const float* wsrc = wd + (size_t)e * HDIM * FDIM + (size_t)(h0 + wrow) * FDIM + wseg * 16;
    uint32_t wdoff = WOFF + (uint32_t)wrow * 80 + (uint32_t)wseg * 32;

    float acc[2][8][4] = {};

    const int NC = FDIM / 32;
    float wcur[16];
    {
        float r[16]; uint4 hv;
        *(float4*)&r[0]  = *(const float4*)(wsrc);
        *(float4*)&r[4]  = *(const float4*)(wsrc + 4);
        *(float4*)&r[8]  = *(const float4*)(wsrc + 8);
        *(float4*)&r[12] = *(const float4*)(wsrc + 12);
        cvt8h(r, hv);     *(uint4*)(smem + wdoff)      = hv;
        cvt8h(r + 8, hv); *(uint4*)(smem + wdoff + 16) = hv;
    }
    cpa16(xdst, xs); cpa16(xdst + 16, xs + 8);
    CP_COMMIT();
    cpa16(xdst + XSTG, xs + 32); cpa16(xdst + XSTG + 16, xs + 40);
    CP_COMMIT();
    *(float4*)&wcur[0]  = *(const float4*)(wsrc + 32);
    *(float4*)&wcur[4]  = *(const float4*)(wsrc + 36);
    *(float4*)&wcur[8]  = *(const float4*)(wsrc + 40);
    *(float4*)&wcur[12] = *(const float4*)(wsrc + 44);
    cp_wait<1>();
    __syncthreads();

    for (int ci = 0; ci < NC; ci++) {
        if (ci + 2 < NC) {
            int kk = (ci + 2) * 32;
            uint32_t so = (uint32_t)((ci + 2) % 3) * XSTG;
            cpa16(xdst + so, xs + kk); cpa16(xdst + so + 16, xs + kk + 8);
            CP_COMMIT();
        }

        const __half* sX = (const __half*)(smem + (ci % 3) * XSTG);
        const __half* sW = (const __half*)(smem + WOFF + (ci & 1) * WSTG);

#pragma unroll
        for (int kt = 0; kt < 2; kt++) {
            int kc = kt * 16 + 2 * q;
            uint32_t ax[2][4];
#pragma unroll
            for (int mt = 0; mt < 2; mt++) {
                int r = wm * 32 + mt * 16 + g;
                ax[mt][0] = *(const uint32_t*)&sX[r*PADK + kc];
                ax[mt][1] = *(const uint32_t*)&sX[(r+8)*PADK + kc];
                ax[mt][2] = *(const uint32_t*)&sX[r*PADK + kc + 8];
                ax[mt][3] = *(const uint32_t*)&sX[(r+8)*PADK + kc + 8];
            }
#pragma unroll
            for (int nt = 0; nt < 8; nt++) {
                int br = wn * 64 + nt * 8 + g;
                uint32_t bw[2] = {*(const uint32_t*)&sW[br*PADK + kc], *(const uint32_t*)&sW[br*PADK + kc + 8]};
#pragma unroll
                for (int mt = 0; mt < 2; mt++)
                    mma16816h(acc[mt][nt], ax[mt], bw);
            }
        }

        if (ci + 1 < NC) {
            uint32_t wo = wdoff + ((ci + 1) & 1) * WSTG;
            uint4 hv;
            cvt8h(wcur, hv);     *(uint4*)(smem + wo)      = hv;
            cvt8h(wcur + 8, hv); *(uint4*)(smem + wo + 16) = hv;
            if (ci + 2 < NC) {
                int kk = (ci + 2) * 32;
                *(float4*)&wcur[0]  = *(const float4*)(wsrc + kk);
                *(float4*)&wcur[4]  = *(const float4*)(wsrc + kk + 4);
                *(float4*)&wcur[8]  = *(const float4*)(wsrc + kk + 8);
                *(float4*)&wcur[12] = *(const float4*)(wsrc + kk + 12);
                cp_wait<1>();
            } else {
                cp_wait<0>();
            }
        }
        __syncthreads();
    }

    // epilogue: y = acc * routing weight -> fp16
#pragma unroll
    for (int mt = 0; mt < 2; mt++) {
        int lm0 = wm * 32 + mt * 16 + g;
        int m = m0 + lm0;
        float w0 = (m     < cnt) ? g_bw[e * T_TOK + m]     : 0.f;
        float w1 = (m + 8 < cnt) ? g_bw[e * T_TOK + m + 8] : 0.f;
#pragma unroll
        for (int nt = 0; nt < 8; nt++) {
            int c = h0 + wn * 64 + nt * 8 + 2 * q;
            float* D = acc[mt][nt];
            if (m < cnt)
                *(__half2*)(g_y + ((size_t)base + m) * HDIM + c) =
                    __floats2half2_rn(D[0] * w0, D[1] * w0);
            if (m + 8 < cnt)
                *(__half2*)(g_y + ((size_t)base + m + 8) * HDIM + c) =
                    __floats2half2_rn(D[2] * w1, D[3] * w1);
        }
    }
}

// ---------------- combine (fp16 reads) ----------------
__global__ void combine_kernel(float* __restrict__ out) {
    int t   = blockIdx.x;
    int tid = threadIdx.x;
    int sl[TOPK];
#pragma unroll
    for (int kk = 0; kk < TOPK; kk++)
        sl[kk] = g_base[g_pe[t*TOPK + kk]] + g_pp[t*TOPK + kk];
    int h = tid * 4;
    float acc0 = 0.f, acc1 = 0.f, acc2 = 0.f, acc3 = 0.f;
#pragma unroll
    for (int kk = 0; kk < TOPK; kk++) {
        const __half2* p = (const __half2*)(g_y + (size_t)sl[kk] * HDIM + h);
        float2 a = __half22float2(p[0]);
        float2 b = __half22float2(p[1]);
        acc0 += a.x; acc1 += a.y; acc2 += b.x; acc3 += b.y;
    }
    *(float4*)(out + (size_t)t * HDIM + h) = make_float4(acc0, acc1, acc2, acc3);
}

// ---------------- launch ----------------
extern "C" void kernel_launch(void* const* d_in, const int* in_sizes, int n_in,
                              void* d_out, int out_size) {
    const float* router_input = (const float*)d_in[0];
    const float* hidden       = (const float*)d_in[1];
    const float* w_router     = (const float*)d_in[2];
    const float* w_gate       = (const float*)d_in[3];
    const float* w_up         = (const float*)d_in[4];
    const float* w_down       = (const float*)d_in[5];
    float* out    = (float*)d_out;
    float* logits = out + (size_t)T_TOK * HDIM;

    static int attr_done = 0;
    if (!attr_done) {
        cudaFuncSetAttribute(gateup_mma, cudaFuncAttributeMaxDynamicSharedMemorySize, GU_SMEM);
        cudaFuncSetAttribute(down_mma,   cudaFuncAttributeMaxDynamicSharedMemorySize, DN_SMEM);
        attr_done = 1;
    }

    __half *x16;
    cudaGetSymbolAddress((void**)&x16, g_x16);

    const int XN8 = T_TOK * HDIM / 8;
    convert_f16<<<XN8 / 256, 256>>>(hidden, x16, XN8);

    zero_cnt<<<1, 32>>>();
    router_gemm<<<T_TOK / 64, 256>>>(router_input, w_router, logits);
    topk_kernel<<<T_TOK / 64, 64>>>(logits);
    prefix_kernel<<<1, 32>>>();
    gateup_mma<<<dim3(FDIM / 64, T_TOK / 128, NE), 256, GU_SMEM>>>(w_gate, w_up);
    down_mma<<<dim3(HDIM / 128, T_TOK / 128, NE), 256, DN_SMEM>>>(w_down);
    combine_kernel<<<T_TOK, 256>>>(out);
}

// round 17
// speedup vs baseline: 1.9497x; 1.0100x over previous
#include <cuda_runtime.h>
#include <cuda_fp16.h>
#include <math.h>
#include <stdint.h>

#define T_TOK 2048
#define HDIM  1024
#define FDIM  512
#define NE    32
#define TOPK  4
#define SLOTS (T_TOK * TOPK)

// ---------------- scratch ----------------
__device__ int   g_cnt[NE];
__device__ int   g_btok[NE * T_TOK];
__device__ float g_bw  [NE * T_TOK];
__device__ int   g_pe  [T_TOK * TOPK];
__device__ int   g_pp  [T_TOK * TOPK];
__device__ __half g_h  [(size_t)SLOTS * FDIM];   // 8 MB
__device__ __half g_y  [(size_t)SLOTS * HDIM];   // 16 MB
__device__ __half g_x16[(size_t)T_TOK * HDIM];   // 4 MB

// ---------------- helpers ----------------
__device__ __forceinline__ void mma16816h(float* d, const uint32_t* a, const uint32_t* b) {
    asm volatile(
        "mma.sync.aligned.m16n8k16.row.col.f32.f16.f16.f32 "
        "{%0,%1,%2,%3}, {%4,%5,%6,%7}, {%8,%9}, {%0,%1,%2,%3};\n"
        : "+f"(d[0]), "+f"(d[1]), "+f"(d[2]), "+f"(d[3])
        : "r"(a[0]), "r"(a[1]), "r"(a[2]), "r"(a[3]), "r"(b[0]), "r"(b[1]));
}

__device__ __forceinline__ uint32_t smem_u32(const void* p) {
    uint32_t a;
    asm("{ .reg .u64 t; cvta.to.shared.u64 t, %1; cvt.u32.u64 %0, t; }" : "=r"(a) : "l"(p));
    return a;
}
__device__ __forceinline__ void cpa16(uint32_t dst, const void* src) {
    asm volatile("cp.async.cg.shared.global [%0], [%1], 16;" :: "r"(dst), "l"(src));
}
#define CP_COMMIT() asm volatile("cp.async.commit_group;" ::: "memory")
template<int N> __device__ __forceinline__ void cp_wait() {
    asm volatile("cp.async.wait_group %0;" :: "n"(N) : "memory");
}

__device__ __forceinline__ void cvt8h(const float* x, uint4& hv) {
    uint32_t h[4];
#pragma unroll
    for (int i = 0; i < 4; i++) {
        __half2 hh = __floats2half2_rn(x[2*i], x[2*i+1]);
        h[i] = *reinterpret_cast<uint32_t*>(&hh);
    }
    hv = make_uint4(h[0], h[1], h[2], h[3]);
}

__device__ __forceinline__ int base_of(int e) {
    int b = 0;
    for (int i = 0; i < e; i++) b += g_cnt[i];
    return b;
}

// ---------------- X conversion + counter zeroing ----------------
__global__ void convert_f16(const float* __restrict__ src,
                            __half* __restrict__ dst, int n8) {
    if (blockIdx.x == 0 && threadIdx.x < NE) g_cnt[threadIdx.x] = 0;
    int i = blockIdx.x * blockDim.x + threadIdx.x;
    if (i >= n8) return;
    float x[8];
    *(float4*)&x[0] = *(const float4*)(src + 8*(size_t)i);
    *(float4*)&x[4] = *(const float4*)(src + 8*(size_t)i + 4);
    uint4 hv; cvt8h(x, hv);
    *(uint4*)(dst + 8*(size_t)i) = hv;
}

// ---------------- router GEMM + fused top-4/softmax/bucketing ----------------
__global__ void router_topk(const float* __restrict__ xr, const float* __restrict__ wr,
                            float* __restrict__ logits) {
    __shared__ float Xs[16][68];
    __shared__ float Ws[16][36];
    __shared__ float Ls[64][33];
    int tid = threadIdx.x;
    int t0  = blockIdx.x * 64;
    int tx = tid & 31, ty = tid >> 5;
    float acc[8];
#pragma unroll
    for (int j = 0; j < 8; j++) acc[j] = 0.f;
    int mL = tid >> 2, ksL = tid & 3;
    for (int k0 = 0; k0 < HDIM; k0 += 16) {
        float4 v = *(const float4*)(xr + (size_t)(t0 + mL) * HDIM + k0 + ksL * 4);
        Xs[ksL*4+0][mL] = v.x; Xs[ksL*4+1][mL] = v.y;
        Xs[ksL*4+2][mL] = v.z; Xs[ksL*4+3][mL] = v.w;
        if (tid < 128) {
            int n = tid >> 2, ks = tid & 3;
            float4 w = *(const float4*)(wr + (size_t)n * HDIM + k0 + ks * 4);
            Ws[ks*4+0][n] = w.x; Ws[ks*4+1][n] = w.y;
            Ws[ks*4+2][n] = w.z; Ws[ks*4+3][n] = w.w;
        }
        __syncthreads();
#pragma unroll
        for (int kk = 0; kk < 16; kk++) {
            float b = Ws[kk][tx];
            float4 a0 = *(const float4*)&Xs[kk][ty*8];
            float4 a1 = *(const float4*)&Xs[kk][ty*8+4];
            acc[0] += a0.x*b; acc[1] += a0.y*b; acc[2] += a0.z*b; acc[3] += a0.w*b;
            acc[4] += a1.x*b; acc[5] += a1.y*b; acc[6] += a1.z*b; acc[7] += a1.w*b;
        }
        __syncthreads();
    }
#pragma unroll
    for (int j = 0; j < 8; j++) {
        logits[(size_t)(t0 + ty*8 + j) * NE + tx] = acc[j];
        Ls[ty*8 + j][tx] = acc[j];
    }
    __syncthreads();

    // fused top-4 + softmax + bucket push (64 threads, one token each)
    if (tid < 64) {
        int t = t0 + tid;
        float v[NE];
#pragma unroll
        for (int e = 0; e < NE; e++) v[e] = Ls[tid][e];
        float val[TOPK]; int sel[TOPK];
#pragma unroll
        for (int kk = 0; kk < TOPK; kk++) {
            float best = -INFINITY; int bi = 0;
#pragma unroll
            for (int e = 0; e < NE; e++)
                if (v[e] > best) { best = v[e]; bi = e; }
            val[kk] = best; sel[kk] = bi; v[bi] = -INFINITY;
        }
        float mx = val[0];
        float w[TOPK], s = 0.f;
#pragma unroll
        for (int kk = 0; kk < TOPK; kk++) { w[kk] = expf(val[kk] - mx); s += w[kk]; }
        float inv = 1.f / s;
#pragma unroll
        for (int kk = 0; kk < TOPK; kk++) {
            int e = sel[kk];
            int pos = atomicAdd(&g_cnt[e], 1);
            g_btok[e * T_TOK + pos] = t;
            g_bw  [e * T_TOK + pos] = w[kk] * inv;
            g_pe[t * TOPK + kk] = e;
            g_pp[t * TOPK + kk] = pos;
        }
    }
}

// ================= gate/up HMMA kernel (fp16 1-pass, 3-stage X, single-sync) =================
#define PADK 40
#define XSTG 10240
#define WOFF 30720
#define WSTG 10240
#define GU_SMEM 51200
#define DN_SMEM 51200
__global__ void __launch_bounds__(256, 2) gateup_mma(
        const float* __restrict__ wg, const float* __restrict__ wu) {
    int e   = blockIdx.z;
    int cnt = g_cnt[e];
    int m0  = blockIdx.y * 128;
    if (m0 >= cnt) return;
    int f0 = blockIdx.x * 64;

    extern __shared__ __align__(128) char smem[];
    uint32_t sb = smem_u32(smem);

    int tid = threadIdx.x, wid = tid >> 5, lane = tid & 31;
    int wm = wid & 3, wn = wid >> 2;
    int g = lane >> 2, q = lane & 3;

    int xrow = tid >> 1, xhalf = tid & 1;
    int tokL = g_btok[e * T_TOK + min(m0 + xrow, cnt - 1)];
    const __half* xs = g_x16 + (size_t)tokL * HDIM + xhalf * 16;
    uint32_t xdst = sb + (uint32_t)xrow * 80 + (uint32_t)xhalf * 32;

    int wrow = tid >> 2, wq = tid & 3;
    const float* gsrc = wg + (size_t)e * FDIM * HDIM + (size_t)(f0 + wrow) * HDIM + wq * 8;
    const float* usrc = wu + (size_t)e * FDIM * HDIM + (size_t)(f0 + wrow) * HDIM + wq * 8;
    uint32_t wdoff = WOFF + (uint32_t)wrow * 80 + (uint32_t)wq * 16;

    float accG[2][4][4] = {}, accU[2][4][4] = {};

    const int NC = HDIM / 32;
    float gcur[8], ucur[8];
    {
        float r[8]; uint4 hv;
        *(float4*)&r[0] = *(const float4*)(gsrc);
        *(float4*)&r[4] = *(const float4*)(gsrc + 4);
        cvt8h(r, hv); *(uint4*)(smem + wdoff)        = hv;
        *(float4*)&r[0] = *(const float4*)(usrc);
        *(float4*)&r[4] = *(const float4*)(usrc + 4);
        cvt8h(r, hv); *(uint4*)(smem + wdoff + 5120) = hv;
    }
    cpa16(xdst, xs); cpa16(xdst + 16, xs + 8);
    CP_COMMIT();
    cpa16(xdst + XSTG, xs + 32); cpa16(xdst + XSTG + 16, xs + 40);
    CP_COMMIT();
    *(float4*)&gcur[0] = *(const float4*)(gsrc + 32);
    *(float4*)&gcur[4] = *(const float4*)(gsrc + 36);
    *(float4*)&ucur[0] = *(const float4*)(usrc + 32);
    *(float4*)&ucur[4] = *(const float4*)(usrc + 36);
    cp_wait<1>();
    __syncthreads();

    for (int ci = 0; ci < NC; ci++) {
        if (ci + 2 < NC) {
            int kk = (ci + 2) * 32;
            uint32_t so = (uint32_t)((ci + 2) % 3) * XSTG;
            cpa16(xdst + so, xs + kk); cpa16(xdst + so + 16, xs + kk + 8);
            CP_COMMIT();
        }

        const __half* sX  = (const __half*)(smem + (ci % 3) * XSTG);
        const __half* sGh = (const __half*)(smem + WOFF + (ci & 1) * WSTG);
        const __half* sUh = (const __half*)(smem + WOFF + (ci & 1) * WSTG + 5120);

#pragma unroll
        for (int kt = 0; kt < 2; kt++) {
            int kc = kt * 16 + 2 * q;
            uint32_t ax[2][4];
#pragma unroll
            for (int mt = 0; mt < 2; mt++) {
                int r = wm * 32 + mt * 16 + g;
                ax[mt][0] = *(const uint32_t*)&sX[r*PADK + kc];
                ax[mt][1] = *(const uint32_t*)&sX[(r+8)*PADK + kc];
                ax[mt][2] = *(const uint32_t*)&sX[r*PADK + kc + 8];
                ax[mt][3] = *(const uint32_t*)&sX[(r+8)*PADK + kc + 8];
            }
#pragma unroll
            for (int nt = 0; nt < 4; nt++) {
                int br = wn * 32 + nt * 8 + g;
                uint32_t bgh[2] = {*(const uint32_t*)&sGh[br*PADK + kc], *(const uint32_t*)&sGh[br*PADK + kc + 8]};
                uint32_t buh[2] = {*(const uint32_t*)&sUh[br*PADK + kc], *(const uint32_t*)&sUh[br*PADK + kc + 8]};
#pragma unroll
                for (int mt = 0; mt < 2; mt++) {
                    mma16816h(accG[mt][nt], ax[mt], bgh);
                    mma16816h(accU[mt][nt], ax[mt], buh);
                }
            }
        }

        if (ci + 1 < NC) {
            uint32_t wo = wdoff + ((ci + 1) & 1) * WSTG;
            uint4 hv;
            cvt8h(gcur, hv); *(uint4*)(smem + wo)        = hv;
            cvt8h(ucur, hv); *(uint4*)(smem + wo + 5120) = hv;
            if (ci + 2 < NC) {
                int kk = (ci + 2) * 32;
                *(float4*)&gcur[0] = *(const float4*)(gsrc + kk);
                *(float4*)&gcur[4] = *(const float4*)(gsrc + kk + 4);
                *(float4*)&ucur[0] = *(const float4*)(usrc + kk);
                *(float4*)&ucur[4] = *(const float4*)(usrc + kk + 4);
                cp_wait<1>();
            } else {
                cp_wait<0>();
            }
        }
        __syncthreads();
    }

    // epilogue: h = relu(G)*U -> fp16
    int base = base_of(e);
#pragma unroll
    for (int mt = 0; mt < 2; mt++) {
        int lm0 = wm * 32 + mt * 16 + g;
#pragma unroll
        for (int nt = 0; nt < 4; nt++) {
            int c = f0 + wn * 32 + nt * 8 + 2 * q;
            float* Gd = accG[mt][nt];
            float* Ud = accU[mt][nt];
            float v0 = fmaxf(Gd[0], 0.f) * Ud[0];
            float v1 = fmaxf(Gd[1], 0.f) * Ud[1];
            float v2 = fmaxf(Gd[2], 0.f) * Ud[2];
            float v3 = fmaxf(Gd[3], 0.f) * Ud[3];
            __half2 h01 = __floats2half2_rn(v0, v1);
            __half2 h23 = __floats2half2_rn(v2, v3);
            int m = m0 + lm0;
            if (m < cnt)
                *(__half2*)(g_h + ((size_t)base + m) * FDIM + c) = h01;
            if (m + 8 < cnt)
                *(__half2*)(g_h + ((size_t)base + m + 8) * FDIM + c) = h23;
        }
    }
}

// ================= down HMMA kernel (fp16 1-pass, BN=128, 3-stage X) =================
__global__ void __launch_bounds__(256, 2) down_mma(const float* __restrict__ wd) {
    int e   = blockIdx.z;
    int cnt = g_cnt[e];
    int m0  = blockIdx.y * 128;
    if (m0 >= cnt) return;
    int h0 = blockIdx.x * 128;

    extern __shared__ __align__(128) char smem[];
    uint32_t sb = smem_u32(smem);

    int tid = threadIdx.x, wid = tid >> 5, lane = tid & 31;
    int wm = wid & 3, wn = wid >> 2;
    int g = lane >> 2, q = lane & 3;
    int base = base_of(e);

    int xrow = tid >> 1, xhalf = tid & 1;
    size_t slotR = (size_t)base + min(m0 + xrow, cnt - 1);
    const __half* xs = g_h + slotR * FDIM + xhalf * 16;
    uint32_t xdst = sb + (uint32_t)xrow * 80 + (uint32_t)xhalf * 32;

    int wrow = tid >> 1, wseg = tid & 1;
    const float* wsrc = wd + (size_t)e * HDIM * FDIM + (size_t)(h0 + wrow) * FDIM + wseg * 16;
    uint32_t wdoff = WOFF + (uint32_t)wrow * 80 + (uint32_t)wseg * 32;

    float acc[2][8][4] = {};

    const int NC = FDIM / 32;
    float wcur[16];
    {
        float r[16]; uint4 hv;
        *(float4*)&r[0]  = *(const float4*)(wsrc);
        *(float4*)&r[4]  = *(const float4*)(wsrc + 4);
        *(float4*)&r[8]  = *(const float4*)(wsrc + 8);
        *(float4*)&r[12] = *(const float4*)(wsrc + 12);
        cvt8h(r, hv);     *(uint4*)(smem + wdoff)      = hv;
        cvt8h(r + 8, hv); *(uint4*)(smem + wdoff + 16) = hv;
    }
    cpa16(xdst, xs); cpa16(xdst + 16, xs + 8);
    CP_COMMIT();
    cpa16(xdst + XSTG, xs + 32); cpa16(xdst + XSTG + 16, xs + 40);
    CP_COMMIT();
    *(float4*)&wcur[0]  = *(const float4*)(wsrc + 32);
    *(float4*)&wcur[4]  = *(const float4*)(wsrc + 36);
    *(float4*)&wcur[8]  = *(const float4*)(wsrc + 40);
    *(float4*)&wcur[12] = *(const float4*)(wsrc + 44);
    cp_wait<1>();
    __syncthreads();

    for (int ci = 0; ci < NC; ci++) {
        if (ci + 2 < NC) {
            int kk = (ci + 2) * 32;
            uint32_t so = (uint32_t)((ci + 2) % 3) * XSTG;
            cpa16(xdst + so, xs + kk); cpa16(xdst + so + 16, xs + kk + 8);
            CP_COMMIT();
        }

        const __half* sX = (const __half*)(smem + (ci % 3) * XSTG);
        const __half* sW = (const __half*)(smem + WOFF + (ci & 1) * WSTG);

#pragma unroll
        for (int kt = 0; kt < 2; kt++) {
            int kc = kt * 16 + 2 * q;
            uint32_t ax[2][4];
#pragma unroll
            for (int mt = 0; mt < 2; mt++) {
                int r = wm * 32 + mt * 16 + g;
                ax[mt][0] = *(const uint32_t*)&sX[r*PADK + kc];
                ax[mt][1] = *(const uint32_t*)&sX[(r+8)*PADK + kc];
                ax[mt][2] = *(const uint32_t*)&sX[r*PADK + kc + 8];
                ax[mt][3] = *(const uint32_t*)&sX[(r+8)*PADK + kc + 8];
            }
#pragma unroll
            for (int nt = 0; nt < 8; nt++) {
                int br = wn * 64 + nt * 8 + g;
                uint32_t bw[2] = {*(const uint32_t*)&sW[br*PADK + kc], *(const uint32_t*)&sW[br*PADK + kc + 8]};
#pragma unroll
                for (int mt = 0; mt < 2; mt++)
                    mma16816h(acc[mt][nt], ax[mt], bw);
            }
        }

        if (ci + 1 < NC) {
            uint32_t wo = wdoff + ((ci + 1) & 1) * WSTG;
            uint4 hv;
            cvt8h(wcur, hv);     *(uint4*)(smem + wo)      = hv;
            cvt8h(wcur + 8, hv); *(uint4*)(smem + wo + 16) = hv;
            if (ci + 2 < NC) {
                int kk = (ci + 2) * 32;
                *(float4*)&wcur[0]  = *(const float4*)(wsrc + kk);
                *(float4*)&wcur[4]  = *(const float4*)(wsrc + kk + 4);
                *(float4*)&wcur[8]  = *(const float4*)(wsrc + kk + 8);
                *(float4*)&wcur[12] = *(const float4*)(wsrc + kk + 12);
                cp_wait<1>();
            } else {
                cp_wait<0>();
            }
        }
        __syncthreads();
    }

    // epilogue: y = acc * routing weight -> fp16
#pragma unroll
    for (int mt = 0; mt < 2; mt++) {
        int lm0 = wm * 32 + mt * 16 + g;
        int m = m0 + lm0;
        float w0 = (m     < cnt) ? g_bw[e * T_TOK + m]     : 0.f;
        float w1 = (m + 8 < cnt) ? g_bw[e * T_TOK + m + 8] : 0.f;
#pragma unroll
        for (int nt = 0; nt < 8; nt++) {
            int c = h0 + wn * 64 + nt * 8 + 2 * q;
            float* D = acc[mt][nt];
            if (m < cnt)
                *(__half2*)(g_y + ((size_t)base + m) * HDIM + c) =
                    __floats2half2_rn(D[0] * w0, D[1] * w0);
            if (m + 8 < cnt)
                *(__half2*)(g_y + ((size_t)base + m + 8) * HDIM + c) =
                    __floats2half2_rn(D[2] * w1, D[3] * w1);
        }
    }
}

// ---------------- combine (fp16 reads, inline prefix) ----------------
__global__ void combine_kernel(float* __restrict__ out) {
    __shared__ int sbase[NE];
    int t   = blockIdx.x;
    int tid = threadIdx.x;
    if (tid < NE) {
        int b = 0;
        for (int i = 0; i < tid; i++) b += g_cnt[i];
        sbase[tid] = b;
    }
    __syncthreads();
    int sl[TOPK];
#pragma unroll
    for (int kk = 0; kk < TOPK; kk++)
        sl[kk] = sbase[g_pe[t*TOPK + kk]] + g_pp[t*TOPK + kk];
    int h = tid * 4;
    float acc0 = 0.f, acc1 = 0.f, acc2 = 0.f, acc3 = 0.f;
#pragma unroll
    for (int kk = 0; kk < TOPK; kk++) {
        const __half2* p = (const __half2*)(g_y + (size_t)sl[kk] * HDIM + h);
        float2 a = __half22float2(p[0]);
        float2 b = __half22float2(p[1]);
        acc0 += a.x; acc1 += a.y; acc2 += b.x; acc3 += b.y;
    }
    *(float4*)(out + (size_t)t * HDIM + h) = make_float4(acc0, acc1, acc2, acc3);
}

// ---------------- launch ----------------
extern "C" void kernel_launch(void* const* d_in, const int* in_sizes, int n_in,
                              void* d_out, int out_size) {
    const float* router_input = (const float*)d_in[0];
    const float* hidden       = (const float*)d_in[1];
    const float* w_router     = (const float*)d_in[2];
    const float* w_gate       = (const float*)d_in[3];
    const float* w_up         = (const float*)d_in[4];
    const float* w_down       = (const float*)d_in[5];
    float* out    = (float*)d_out;
    float* logits = out + (size_t)T_TOK * HDIM;

    static int attr_done = 0;
    if (!attr_done) {
        cudaFuncSetAttribute(gateup_mma, cudaFuncAttributeMaxDynamicSharedMemorySize, GU_SMEM);
        cudaFuncSetAttribute(down_mma,   cudaFuncAttributeMaxDynamicSharedMemorySize, DN_SMEM);
        attr_done = 1;
    }

    __half *x16;
    cudaGetSymbolAddress((void**)&x16, g_x16);

    const int XN8 = T_TOK * HDIM / 8;
    convert_f16<<<XN8 / 256, 256>>>(hidden, x16, XN8);
    router_topk<<<T_TOK / 64, 256>>>(router_input, w_router, logits);
    gateup_mma<<<dim3(FDIM / 64, T_TOK / 128, NE), 256, GU_SMEM>>>(w_gate, w_up);
    down_mma<<<dim3(HDIM / 128, T_TOK / 128, NE), 256, DN_SMEM>>>(w_down);
    combine_kernel<<<T_TOK, 256>>>(out);
}